// round 5
// baseline (speedup 1.0000x reference)
#include <cuda_runtime.h>
#include <cuda_fp16.h>
#include <cstdint>
#include <cstddef>

// ---------------------------------------------------------------------------
// Problem constants: B=16, L=4096, D=H=512
// ---------------------------------------------------------------------------
constexpr int Bb   = 16;
constexpr int Lseq = 4096;
constexpr int Dm   = 512;
constexpr int Hh   = 512;
constexpr int MROWS = Bb * Lseq;          // 65536
constexpr int DFF  = 2048;                // 4*D
constexpr int NSEG = 8;
constexpr int SEGL = Lseq / NSEG;         // 512
constexpr int NCH  = Bb * Hh;             // 8192 scan chains

// ---------------------------------------------------------------------------
// Scratch (device globals)
// ---------------------------------------------------------------------------
__device__ __align__(16) __half g_Xh   [(size_t)MROWS * Dm];
__device__ __align__(16) __half g_Wsruh[(size_t)Dm * 3 * Hh];
__device__ __align__(16) __half g_W1h  [(size_t)Dm * DFF];
__device__ __align__(16) __half g_W2h  [(size_t)DFF * Dm];
__device__ __align__(16) __half g_Zh   [(size_t)MROWS * Hh];
__device__ __align__(16) __half g_Fh   [(size_t)MROWS * Hh];
__device__ __align__(16) __half g_Rh   [(size_t)MROWS * Hh];
__device__ __align__(16) float  g_HW   [(size_t)MROWS * Dm];
__device__ __align__(16) __half g_X1h  [(size_t)MROWS * Dm];
__device__ __align__(16) __half g_H4h  [(size_t)MROWS * DFF];
__device__ __align__(16) float  g_X2   [(size_t)MROWS * Dm];
__device__ float g_cend [NCH * NSEG];
__device__ float g_pend [NCH * NSEG];
__device__ float g_carry[NCH * NSEG];

// ---------------------------------------------------------------------------
// Helpers
// ---------------------------------------------------------------------------
__device__ __forceinline__ void cp16(uint32_t dst_s, const void* src) {
    asm volatile("cp.async.cg.shared.global [%0], [%1], 16;\n" :: "r"(dst_s), "l"(src));
}
__device__ __forceinline__ void cp_commit() { asm volatile("cp.async.commit_group;\n"); }
template<int NN>
__device__ __forceinline__ void cp_wait() { asm volatile("cp.async.wait_group %0;\n" :: "n"(NN)); }

__device__ __forceinline__ void ldsm_x4(uint32_t& r0, uint32_t& r1, uint32_t& r2, uint32_t& r3,
                                        uint32_t addr) {
    asm volatile("ldmatrix.sync.aligned.m8n8.x4.shared.b16 {%0,%1,%2,%3},[%4];\n"
                 : "=r"(r0), "=r"(r1), "=r"(r2), "=r"(r3) : "r"(addr));
}
__device__ __forceinline__ void ldsm_x4t(uint32_t& r0, uint32_t& r1, uint32_t& r2, uint32_t& r3,
                                         uint32_t addr) {
    asm volatile("ldmatrix.sync.aligned.m8n8.x4.trans.shared.b16 {%0,%1,%2,%3},[%4];\n"
                 : "=r"(r0), "=r"(r1), "=r"(r2), "=r"(r3) : "r"(addr));
}
__device__ __forceinline__ void mma16(float* c, const uint32_t* a, const uint32_t* b) {
    asm volatile(
        "mma.sync.aligned.m16n8k16.row.col.f32.f16.f16.f32 "
        "{%0,%1,%2,%3},{%4,%5,%6,%7},{%8,%9},{%0,%1,%2,%3};\n"
        : "+f"(c[0]), "+f"(c[1]), "+f"(c[2]), "+f"(c[3])
        : "r"(a[0]), "r"(a[1]), "r"(a[2]), "r"(a[3]), "r"(b[0]), "r"(b[1]));
}

__device__ __forceinline__ float sigmoidf_(float v) { return 1.0f / (1.0f + expf(-v)); }
__device__ __forceinline__ float gelu_(float v) {
    return 0.5f * v * (1.0f + erff(v * 0.70710678118654752440f));
}

// ---------------------------------------------------------------------------
// fp32 -> fp16 (8 elems/thread)
// ---------------------------------------------------------------------------
__global__ void f2h(const float* __restrict__ in, __half* __restrict__ out, int n8) {
    int i = blockIdx.x * blockDim.x + threadIdx.x;
    if (i >= n8) return;
    const float4* src = (const float4*)in + i * 2;
    float4 a = src[0], b = src[1];
    __half2 h[4];
    h[0] = __floats2half2_rn(a.x, a.y);
    h[1] = __floats2half2_rn(a.z, a.w);
    h[2] = __floats2half2_rn(b.x, b.y);
    h[3] = __floats2half2_rn(b.z, b.w);
    ((uint4*)out)[i] = *(uint4*)h;
}

// ---------------------------------------------------------------------------
// fp16 GEMM: C[M,N] = A[M,K] @ W[K,N], fused epilogues.
// CTA tile 128x256x64, 8 warps each 64x64, 3-stage cp.async pipeline,
// XOR-swizzled smem, ldmatrix fragment loads.
//   EPI=0: SRU proj -> g_Zh | g_Fh=sig(+b_f) | g_Rh=sig(+b_r)   (A = g_Xh)
//   EPI=1: MLP up   -> g_H4h = gelu(v + b1)                     (A = g_X1h)
//   EPI=2: MLP down -> g_X2  = v + b2 + x1 (fp32)               (A = g_H4h)
// ---------------------------------------------------------------------------
constexpr int BM = 128, BN = 256, BK = 64;
constexpr int STG_BYTES = BM * BK * 2 + BK * BN * 2;   // 16KB + 32KB = 48KB
constexpr int GSMEM = 3 * STG_BYTES;                    // 144KB dynamic

// A smem: 128 rows x 64 fp16 (128B/row, 8x16B chunks)
__device__ __forceinline__ uint32_t aoff(int r, int c) {
    return (uint32_t)(r * 128 + ((c ^ (r & 7)) << 4));
}
// B smem: 64 rows x 256 fp16 (512B/row, 32x16B chunks)
__device__ __forceinline__ uint32_t boff(int k, int c) {
    return (uint32_t)(k * 512 + ((c ^ (k & 7)) << 4));
}

template<int EPI, int N, int K>
__global__ __launch_bounds__(256, 1) void gemm_h(
    const float* __restrict__ bias,
    const float* __restrict__ bias2)
{
    extern __shared__ __align__(1024) char dsm[];

    const __half* __restrict__ A =
        (EPI == 0) ? g_Xh : ((EPI == 1) ? g_X1h : g_H4h);
    const __half* __restrict__ W =
        (EPI == 0) ? g_Wsruh : ((EPI == 1) ? g_W1h : g_W2h);

    const int t    = threadIdx.x;
    const int m0   = blockIdx.y * BM;
    const int n0   = blockIdx.x * BN;
    const int lane = t & 31, wid = t >> 5;
    const int gq   = lane >> 2, tg = lane & 3;
    const int wm   = (wid >> 2) * 64;   // 2 m-groups
    const int wn   = (wid & 3) * 64;    // 4 n-groups

    const uint32_t sBase = (uint32_t)__cvta_generic_to_shared(dsm);

    float acc[4][8][4];
    #pragma unroll
    for (int i = 0; i < 4; i++)
        #pragma unroll
        for (int j = 0; j < 8; j++)
            #pragma unroll
            for (int r = 0; r < 4; r++) acc[i][j][r] = 0.0f;

    auto loadChunk = [&](int kt, int s) {
        const uint32_t aB = sBase + (uint32_t)s * STG_BYTES;
        const uint32_t bB = aB + BM * BK * 2;
        #pragma unroll
        for (int i = 0; i < 4; i++) {              // A: 128x64 fp16 = 1024 x 16B
            int idx = t + i * 256;
            int row = idx >> 3, c = idx & 7;
            cp16(aB + aoff(row, c),
                 A + (size_t)(m0 + row) * K + (size_t)kt * BK + c * 8);
        }
        #pragma unroll
        for (int i = 0; i < 8; i++) {              // B: 64x256 fp16 = 2048 x 16B
            int idx = t + i * 256;
            int row = idx >> 5, c = idx & 31;
            cp16(bB + boff(row, c),
                 W + (size_t)((size_t)kt * BK + row) * N + n0 + c * 8);
        }
        cp_commit();
    };

    const int KT = K / BK;
    loadChunk(0, 0);
    if (KT > 1) loadChunk(1, 1);

    const int ltile = lane >> 3;       // 0..3
    const int lrow  = lane & 7;

    for (int kt = 0; kt < KT; ++kt) {
        if (kt + 2 <= KT) cp_wait<1>(); else cp_wait<0>();
        __syncthreads();
        if (kt + 2 < KT) loadChunk(kt + 2, (kt + 2) % 3);

        const uint32_t aBase = sBase + (uint32_t)((kt % 3) * STG_BYTES);
        const uint32_t bBase = aBase + BM * BK * 2;

        #pragma unroll
        for (int ks = 0; ks < 4; ++ks) {           // four k16 steps in BK=64
            uint32_t af[4][4], bf[8][2];
            #pragma unroll
            for (int mi = 0; mi < 4; mi++) {
                int row = wm + mi * 16 + ((ltile & 1) << 3) + lrow;
                int c   = ks * 2 + (ltile >> 1);
                ldsm_x4(af[mi][0], af[mi][1], af[mi][2], af[mi][3],
                        aBase + aoff(row, c));
            }
            #pragma unroll
            for (int ni2 = 0; ni2 < 4; ni2++) {
                int k = ks * 16 + ((ltile & 1) << 3) + lrow;
                int c = (wn >> 3) + ni2 * 2 + (ltile >> 1);
                uint32_t r0, r1, r2, r3;
                ldsm_x4t(r0, r1, r2, r3, bBase + boff(k, c));
                bf[ni2 * 2 + 0][0] = r0; bf[ni2 * 2 + 0][1] = r1;
                bf[ni2 * 2 + 1][0] = r2; bf[ni2 * 2 + 1][1] = r3;
            }
            #pragma unroll
            for (int mi = 0; mi < 4; mi++)
                #pragma unroll
                for (int ni = 0; ni < 8; ni++)
                    mma16(acc[mi][ni], af[mi], bf[ni]);
        }
    }

    // Epilogue: acc c0,c1 @ row gq col 2tg; c2,c3 @ row gq+8
    #pragma unroll
    for (int mi = 0; mi < 4; mi++) {
        #pragma unroll
        for (int ni = 0; ni < 8; ni++) {
            #pragma unroll
            for (int half = 0; half < 2; half++) {
                int row = m0 + wm + mi * 16 + gq + half * 8;
                int col = n0 + wn + ni * 8 + tg * 2;
                float v0 = acc[mi][ni][half * 2 + 0];
                float v1 = acc[mi][ni][half * 2 + 1];
                size_t rw = (size_t)row;
                if (EPI == 0) {
                    if (col < Hh) {
                        *(__half2*)(g_Zh + rw * Hh + col) = __floats2half2_rn(v0, v1);
                    } else if (col < 2 * Hh) {
                        int h = col - Hh;
                        *(__half2*)(g_Fh + rw * Hh + h) = __floats2half2_rn(
                            sigmoidf_(v0 + bias[h]), sigmoidf_(v1 + bias[h + 1]));
                    } else {
                        int h = col - 2 * Hh;
                        *(__half2*)(g_Rh + rw * Hh + h) = __floats2half2_rn(
                            sigmoidf_(v0 + bias2[h]), sigmoidf_(v1 + bias2[h + 1]));
                    }
                } else if (EPI == 1) {
                    *(__half2*)(g_H4h + rw * N + col) = __floats2half2_rn(
                        gelu_(v0 + bias[col]), gelu_(v1 + bias[col + 1]));
                } else {
                    __half2 x1 = *(const __half2*)(g_X1h + rw * N + col);
                    float2 o;
                    o.x = v0 + bias[col]     + __half2float(__low2half(x1));
                    o.y = v1 + bias[col + 1] + __half2float(__high2half(x1));
                    *(float2*)(g_X2 + rw * N + col) = o;
                }
            }
        }
    }
}

// ---------------------------------------------------------------------------
// Segmented SRU scan (exact, 3 passes)
// ---------------------------------------------------------------------------
__global__ void scanA()
{
    int t = blockIdx.x * blockDim.x + threadIdx.x;   // 0..65535
    int q = t & (NCH - 1);
    int s = t >> 13;
    int b = q >> 9;
    int h = q & (Hh - 1);
    size_t base = ((size_t)b * Lseq + (size_t)s * SEGL) * Hh + h;

    float c = 0.0f, p = 1.0f;
    #pragma unroll 8
    for (int l = 0; l < SEGL; ++l) {
        size_t i = base + (size_t)l * Hh;
        float f = __half2float(g_Fh[i]);
        float z = __half2float(g_Zh[i]);
        c = fmaf(f, c - z, z);
        p *= f;
    }
    g_cend[t] = c;
    g_pend[t] = p;
}

__global__ void scanB()
{
    int q = blockIdx.x * blockDim.x + threadIdx.x;   // 0..8191
    float carry = 0.0f;
    #pragma unroll
    for (int s = 0; s < NSEG; ++s) {
        int idx = s * NCH + q;
        g_carry[idx] = carry;
        carry = g_cend[idx] + g_pend[idx] * carry;
    }
}

__global__ void scanC(const float* __restrict__ x)
{
    int t = blockIdx.x * blockDim.x + threadIdx.x;   // 0..65535
    int q = t & (NCH - 1);
    int s = t >> 13;
    int b = q >> 9;
    int h = q & (Hh - 1);
    size_t base = ((size_t)b * Lseq + (size_t)s * SEGL) * Hh + h;

    float c = g_carry[s * NCH + q];
    #pragma unroll 8
    for (int l = 0; l < SEGL; ++l) {
        size_t i = base + (size_t)l * Hh;
        float f  = __half2float(g_Fh[i]);
        float z  = __half2float(g_Zh[i]);
        float r  = __half2float(g_Rh[i]);
        float xv = x[i];
        c = fmaf(f, c - z, z);
        g_HW[i] = fmaf(r, c - xv, 2.0f * xv);
    }
}

// ---------------------------------------------------------------------------
// LayerNorm over 512: 1 block/row, 128 threads x float4.
// ---------------------------------------------------------------------------
template<int WHICH>
__global__ void ln512(const float* __restrict__ gamma,
                      const float* __restrict__ beta,
                      float* __restrict__ outp)
{
    const float* in = (WHICH == 0) ? (const float*)g_HW : (const float*)g_X2;

    size_t row = blockIdx.x;
    int t = threadIdx.x;

    float4 v = ((const float4*)(in + row * Dm))[t];
    float s  = v.x + v.y + v.z + v.w;
    float sq = v.x*v.x + v.y*v.y + v.z*v.z + v.w*v.w;

    #pragma unroll
    for (int o = 16; o > 0; o >>= 1) {
        s  += __shfl_xor_sync(0xffffffffu, s,  o);
        sq += __shfl_xor_sync(0xffffffffu, sq, o);
    }
    __shared__ float ssum[4], ssq[4];
    int w = t >> 5;
    if ((t & 31) == 0) { ssum[w] = s; ssq[w] = sq; }
    __syncthreads();
    float S  = ssum[0] + ssum[1] + ssum[2] + ssum[3];
    float SQ = ssq[0] + ssq[1] + ssq[2] + ssq[3];

    float mean = S * (1.0f / 512.0f);
    float var  = SQ * (1.0f / 512.0f) - mean * mean;
    float rstd = rsqrtf(var + 1e-5f);

    float4 gg = ((const float4*)gamma)[t];
    float4 bb = ((const float4*)beta)[t];
    float4 o4;
    o4.x = (v.x - mean) * rstd * gg.x + bb.x;
    o4.y = (v.y - mean) * rstd * gg.y + bb.y;
    o4.z = (v.z - mean) * rstd * gg.z + bb.z;
    o4.w = (v.w - mean) * rstd * gg.w + bb.w;

    if (WHICH == 0) {
        __half2 h0 = __floats2half2_rn(o4.x, o4.y);
        __half2 h1 = __floats2half2_rn(o4.z, o4.w);
        uint2 pk = { *(uint32_t*)&h0, *(uint32_t*)&h1 };
        ((uint2*)(g_X1h + row * Dm))[t] = pk;
    } else {
        ((float4*)(outp + row * Dm))[t] = o4;
    }
}

// ---------------------------------------------------------------------------
// Launch
// ---------------------------------------------------------------------------
extern "C" void kernel_launch(void* const* d_in, const int* in_sizes, int n_in,
                              void* d_out, int out_size)
{
    const float* x    = (const float*)d_in[0];
    const float* Wsru = (const float*)d_in[1];
    const float* b_f  = (const float*)d_in[2];
    const float* b_r  = (const float*)d_in[3];
    const float* ln1g = (const float*)d_in[4];
    const float* ln1b = (const float*)d_in[5];
    const float* W1   = (const float*)d_in[6];
    const float* b1   = (const float*)d_in[7];
    const float* W2   = (const float*)d_in[8];
    const float* b2   = (const float*)d_in[9];
    const float* ln2g = (const float*)d_in[10];
    const float* ln2b = (const float*)d_in[11];
    float* out = (float*)d_out;

    static bool attr_done = false;
    if (!attr_done) {
        cudaFuncSetAttribute(gemm_h<0, 3 * Hh, Dm>,
                             cudaFuncAttributeMaxDynamicSharedMemorySize, GSMEM);
        cudaFuncSetAttribute(gemm_h<1, DFF, Dm>,
                             cudaFuncAttributeMaxDynamicSharedMemorySize, GSMEM);
        cudaFuncSetAttribute(gemm_h<2, Dm, DFF>,
                             cudaFuncAttributeMaxDynamicSharedMemorySize, GSMEM);
        attr_done = true;
    }

    __half* dXh; __half* dWsru; __half* dW1; __half* dW2;
    cudaGetSymbolAddress((void**)&dXh,   g_Xh);
    cudaGetSymbolAddress((void**)&dWsru, g_Wsruh);
    cudaGetSymbolAddress((void**)&dW1,   g_W1h);
    cudaGetSymbolAddress((void**)&dW2,   g_W2h);

    // 0) fp32 -> fp16 pre-pass (x + all weights)
    {
        int n8 = (MROWS * Dm) / 8;
        f2h<<<(n8 + 255) / 256, 256>>>(x, dXh, n8);
        n8 = (Dm * 3 * Hh) / 8;
        f2h<<<(n8 + 255) / 256, 256>>>(Wsru, dWsru, n8);
        n8 = (Dm * DFF) / 8;
        f2h<<<(n8 + 255) / 256, 256>>>(W1, dW1, n8);
        n8 = (DFF * Dm) / 8;
        f2h<<<(n8 + 255) / 256, 256>>>(W2, dW2, n8);
    }

    // 1) u = x @ W_sru, fused gate sigmoids -> g_Zh/g_Fh/g_Rh
    gemm_h<0, 3 * Hh, Dm><<<dim3((3 * Hh) / BN, MROWS / BM), 256, GSMEM>>>(b_f, b_r);
    // 2) segmented recurrence + highway -> g_HW
    scanA<<<(NCH * NSEG) / 256, 256>>>();
    scanB<<<NCH / 256, 256>>>();
    scanC<<<(NCH * NSEG) / 256, 256>>>(x);
    // 3) LN1 -> g_X1h
    ln512<0><<<MROWS, 128>>>(ln1g, ln1b, nullptr);
    // 4) h = gelu(x1 @ W1 + b1) -> g_H4h
    gemm_h<1, DFF, Dm><<<dim3(DFF / BN, MROWS / BM), 256, GSMEM>>>(b1, nullptr);
    // 5) x2 = x1 + h @ W2 + b2 -> g_X2
    gemm_h<2, Dm, DFF><<<dim3(Dm / BN, MROWS / BM), 256, GSMEM>>>(b2, nullptr);
    // 6) LN2 -> d_out
    ln512<1><<<MROWS, 128>>>(ln2g, ln2b, out);
}

// round 6
// speedup vs baseline: 1.1772x; 1.1772x over previous
#include <cuda_runtime.h>
#include <cuda_fp16.h>
#include <cstdint>
#include <cstddef>

// ---------------------------------------------------------------------------
// Problem constants: B=16, L=4096, D=H=512
// ---------------------------------------------------------------------------
constexpr int Bb   = 16;
constexpr int Lseq = 4096;
constexpr int Dm   = 512;
constexpr int Hh   = 512;
constexpr int MROWS = Bb * Lseq;          // 65536
constexpr int DFF  = 2048;                // 4*D
constexpr int NSEG = 8;
constexpr int SEGL = Lseq / NSEG;         // 512
constexpr int NCH  = Bb * Hh;             // 8192 scan chains

// ---------------------------------------------------------------------------
// Scratch (device globals)
// ---------------------------------------------------------------------------
__device__ __align__(16) __half g_Xh   [(size_t)MROWS * Dm];
__device__ __align__(16) __half g_Wsruh[(size_t)Dm * 3 * Hh];
__device__ __align__(16) __half g_W1h  [(size_t)Dm * DFF];
__device__ __align__(16) __half g_W2h  [(size_t)DFF * Dm];
__device__ __align__(16) __half g_Zh   [(size_t)MROWS * Hh];
__device__ __align__(16) __half g_Fh   [(size_t)MROWS * Hh];
__device__ __align__(16) __half g_Rh   [(size_t)MROWS * Hh];
__device__ __align__(16) __half g_X1h  [(size_t)MROWS * Dm];
__device__ __align__(16) __half g_H4h  [(size_t)MROWS * DFF];
__device__ __align__(16) float  g_X2   [(size_t)MROWS * Dm];
__device__ float g_cend [NCH * NSEG];
__device__ float g_pend [NCH * NSEG];
__device__ float g_carry[NCH * NSEG];

// ---------------------------------------------------------------------------
// Helpers
// ---------------------------------------------------------------------------
__device__ __forceinline__ void cp16(uint32_t dst_s, const void* src) {
    asm volatile("cp.async.cg.shared.global [%0], [%1], 16;\n" :: "r"(dst_s), "l"(src));
}
__device__ __forceinline__ void cp_commit() { asm volatile("cp.async.commit_group;\n"); }
template<int NN>
__device__ __forceinline__ void cp_wait() { asm volatile("cp.async.wait_group %0;\n" :: "n"(NN)); }

__device__ __forceinline__ void ldsm_x4(uint32_t& r0, uint32_t& r1, uint32_t& r2, uint32_t& r3,
                                        uint32_t addr) {
    asm volatile("ldmatrix.sync.aligned.m8n8.x4.shared.b16 {%0,%1,%2,%3},[%4];\n"
                 : "=r"(r0), "=r"(r1), "=r"(r2), "=r"(r3) : "r"(addr));
}
__device__ __forceinline__ void ldsm_x4t(uint32_t& r0, uint32_t& r1, uint32_t& r2, uint32_t& r3,
                                         uint32_t addr) {
    asm volatile("ldmatrix.sync.aligned.m8n8.x4.trans.shared.b16 {%0,%1,%2,%3},[%4];\n"
                 : "=r"(r0), "=r"(r1), "=r"(r2), "=r"(r3) : "r"(addr));
}
__device__ __forceinline__ void mma16(float* c, const uint32_t* a, const uint32_t* b) {
    asm volatile(
        "mma.sync.aligned.m16n8k16.row.col.f32.f16.f16.f32 "
        "{%0,%1,%2,%3},{%4,%5,%6,%7},{%8,%9},{%0,%1,%2,%3};\n"
        : "+f"(c[0]), "+f"(c[1]), "+f"(c[2]), "+f"(c[3])
        : "r"(a[0]), "r"(a[1]), "r"(a[2]), "r"(a[3]), "r"(b[0]), "r"(b[1]));
}

__device__ __forceinline__ float sigmoidf_(float v) { return 1.0f / (1.0f + expf(-v)); }
__device__ __forceinline__ float gelu_(float v) {
    return 0.5f * v * (1.0f + erff(v * 0.70710678118654752440f));
}

// ---------------------------------------------------------------------------
// fp32 -> fp16 (8 elems/thread)
// ---------------------------------------------------------------------------
__global__ void f2h(const float* __restrict__ in, __half* __restrict__ out, int n8) {
    int i = blockIdx.x * blockDim.x + threadIdx.x;
    if (i >= n8) return;
    const float4* src = (const float4*)in + i * 2;
    float4 a = src[0], b = src[1];
    __half2 h[4];
    h[0] = __floats2half2_rn(a.x, a.y);
    h[1] = __floats2half2_rn(a.z, a.w);
    h[2] = __floats2half2_rn(b.x, b.y);
    h[3] = __floats2half2_rn(b.z, b.w);
    ((uint4*)out)[i] = *(uint4*)h;
}

// ---------------------------------------------------------------------------
// fp16 GEMM (R4-proven config): C[M,N] = A[M,K] @ W[K,N], fused epilogues.
// Tile 128x128x64, 3-stage cp.async pipeline, 256 threads (2x4 warps @ 64x32),
// XOR-swizzled smem, ldmatrix fragment loads, 2 CTAs/SM.
//   EPI=0: SRU proj -> g_Zh | g_Fh=sig(+b_f) | g_Rh=sig(+b_r)   (A = g_Xh)
//   EPI=1: MLP up   -> g_H4h = gelu(v + b1)                     (A = g_X1h)
//   EPI=2: MLP down -> g_X2  = v + b2 + x1 (fp32)               (A = g_H4h)
// ---------------------------------------------------------------------------
constexpr int BM = 128, BN = 128, BK = 64;
constexpr int STG_BYTES = BM * BK * 2 + BK * BN * 2;   // 16KB + 16KB = 32KB
constexpr int GSMEM = 3 * STG_BYTES;                    // 96KB dynamic

// A smem: 128 rows x 64 fp16 (128B/row, 8x16B chunks)
__device__ __forceinline__ uint32_t aoff(int r, int c) {
    return (uint32_t)(r * 128 + ((c ^ (r & 7)) << 4));
}
// B smem: 64 rows x 128 fp16 (256B/row, 16x16B chunks)
__device__ __forceinline__ uint32_t boff(int k, int c) {
    return (uint32_t)(k * 256 + ((c ^ (k & 7)) << 4));
}

template<int EPI, int N, int K>
__global__ __launch_bounds__(256, 2) void gemm_h(
    const float* __restrict__ bias,
    const float* __restrict__ bias2)
{
    extern __shared__ __align__(1024) char dsm[];

    const __half* __restrict__ A =
        (EPI == 0) ? g_Xh : ((EPI == 1) ? g_X1h : g_H4h);
    const __half* __restrict__ W =
        (EPI == 0) ? g_Wsruh : ((EPI == 1) ? g_W1h : g_W2h);

    const int t    = threadIdx.x;
    const int m0   = blockIdx.y * BM;
    const int n0   = blockIdx.x * BN;
    const int lane = t & 31, wid = t >> 5;
    const int gq   = lane >> 2, tg = lane & 3;
    const int wm   = (wid >> 2) * 64;   // warp m offset
    const int wn   = (wid & 3) * 32;    // warp n offset

    const uint32_t sBase = (uint32_t)__cvta_generic_to_shared(dsm);

    float acc[4][4][4];
    #pragma unroll
    for (int i = 0; i < 4; i++)
        #pragma unroll
        for (int j = 0; j < 4; j++)
            #pragma unroll
            for (int r = 0; r < 4; r++) acc[i][j][r] = 0.0f;

    auto loadChunk = [&](int kt, int s) {
        const uint32_t aB = sBase + (uint32_t)s * STG_BYTES;
        const uint32_t bB = aB + BM * BK * 2;
        #pragma unroll
        for (int i = 0; i < 4; i++) {              // A: 128x64 fp16 = 1024 x 16B
            int idx = t + i * 256;
            int row = idx >> 3, c = idx & 7;
            cp16(aB + aoff(row, c),
                 A + (size_t)(m0 + row) * K + (size_t)kt * BK + c * 8);
        }
        #pragma unroll
        for (int i = 0; i < 4; i++) {              // B: 64x128 fp16 = 1024 x 16B
            int idx = t + i * 256;
            int row = idx >> 4, c = idx & 15;
            cp16(bB + boff(row, c),
                 W + (size_t)((size_t)kt * BK + row) * N + n0 + c * 8);
        }
        cp_commit();
    };

    const int KT = K / BK;
    loadChunk(0, 0);
    if (KT > 1) loadChunk(1, 1);

    const int ltile = lane >> 3;       // 0..3
    const int lrow  = lane & 7;

    for (int kt = 0; kt < KT; ++kt) {
        if (kt + 2 <= KT) cp_wait<1>(); else cp_wait<0>();
        __syncthreads();
        if (kt + 2 < KT) loadChunk(kt + 2, (kt + 2) % 3);

        const uint32_t aBase = sBase + (uint32_t)((kt % 3) * STG_BYTES);
        const uint32_t bBase = aBase + BM * BK * 2;

        #pragma unroll
        for (int ks = 0; ks < 4; ++ks) {           // four k16 steps in BK=64
            uint32_t af[4][4], bf[4][2];
            #pragma unroll
            for (int mi = 0; mi < 4; mi++) {
                int row = wm + mi * 16 + ((ltile & 1) << 3) + lrow;
                int c   = ks * 2 + (ltile >> 1);
                ldsm_x4(af[mi][0], af[mi][1], af[mi][2], af[mi][3],
                        aBase + aoff(row, c));
            }
            #pragma unroll
            for (int ni2 = 0; ni2 < 2; ni2++) {
                int k = ks * 16 + ((ltile & 1) << 3) + lrow;
                int c = (wn >> 3) + ni2 * 2 + (ltile >> 1);
                uint32_t r0, r1, r2, r3;
                ldsm_x4t(r0, r1, r2, r3, bBase + boff(k, c));
                bf[ni2 * 2 + 0][0] = r0; bf[ni2 * 2 + 0][1] = r1;
                bf[ni2 * 2 + 1][0] = r2; bf[ni2 * 2 + 1][1] = r3;
            }
            #pragma unroll
            for (int mi = 0; mi < 4; mi++)
                #pragma unroll
                for (int ni = 0; ni < 4; ni++)
                    mma16(acc[mi][ni], af[mi], bf[ni]);
        }
    }

    // Epilogue: acc c0,c1 @ row gq col 2tg; c2,c3 @ row gq+8
    #pragma unroll
    for (int mi = 0; mi < 4; mi++) {
        #pragma unroll
        for (int ni = 0; ni < 4; ni++) {
            #pragma unroll
            for (int half = 0; half < 2; half++) {
                int row = m0 + wm + mi * 16 + gq + half * 8;
                int col = n0 + wn + ni * 8 + tg * 2;
                float v0 = acc[mi][ni][half * 2 + 0];
                float v1 = acc[mi][ni][half * 2 + 1];
                size_t rw = (size_t)row;
                if (EPI == 0) {
                    if (col < Hh) {
                        *(__half2*)(g_Zh + rw * Hh + col) = __floats2half2_rn(v0, v1);
                    } else if (col < 2 * Hh) {
                        int h = col - Hh;
                        *(__half2*)(g_Fh + rw * Hh + h) = __floats2half2_rn(
                            sigmoidf_(v0 + bias[h]), sigmoidf_(v1 + bias[h + 1]));
                    } else {
                        int h = col - 2 * Hh;
                        *(__half2*)(g_Rh + rw * Hh + h) = __floats2half2_rn(
                            sigmoidf_(v0 + bias2[h]), sigmoidf_(v1 + bias2[h + 1]));
                    }
                } else if (EPI == 1) {
                    *(__half2*)(g_H4h + rw * N + col) = __floats2half2_rn(
                        gelu_(v0 + bias[col]), gelu_(v1 + bias[col + 1]));
                } else {
                    __half2 x1 = *(const __half2*)(g_X1h + rw * N + col);
                    float2 o;
                    o.x = v0 + bias[col]     + __half2float(__low2half(x1));
                    o.y = v1 + bias[col + 1] + __half2float(__high2half(x1));
                    *(float2*)(g_X2 + rw * N + col) = o;
                }
            }
        }
    }
}

// ---------------------------------------------------------------------------
// Segmented SRU scan, passes A and B (exact)
// ---------------------------------------------------------------------------
__global__ void scanA()
{
    int t = blockIdx.x * blockDim.x + threadIdx.x;   // 0..65535
    int q = t & (NCH - 1);
    int s = t >> 13;
    int b = q >> 9;
    int h = q & (Hh - 1);
    size_t base = ((size_t)b * Lseq + (size_t)s * SEGL) * Hh + h;

    float c = 0.0f, p = 1.0f;
    #pragma unroll 8
    for (int l = 0; l < SEGL; ++l) {
        size_t i = base + (size_t)l * Hh;
        float f = __half2float(g_Fh[i]);
        float z = __half2float(g_Zh[i]);
        c = fmaf(f, c - z, z);
        p *= f;
    }
    g_cend[t] = c;
    g_pend[t] = p;
}

__global__ void scanB()
{
    int q = blockIdx.x * blockDim.x + threadIdx.x;   // 0..8191
    float carry = 0.0f;
    #pragma unroll
    for (int s = 0; s < NSEG; ++s) {
        int idx = s * NCH + q;
        g_carry[idx] = carry;
        carry = g_cend[idx] + g_pend[idx] * carry;
    }
}

// ---------------------------------------------------------------------------
// Pass C fused with LayerNorm1.  Block = (b, seg): 512 threads, one per h.
// Walks SEGL timesteps; per step computes recurrence + highway in fp32,
// block-reduces mean/var (1 __syncthreads, double-buffered smem), writes
// LN1 output directly to g_X1h (fp16).  g_HW is eliminated entirely.
// ---------------------------------------------------------------------------
__global__ __launch_bounds__(512, 1) void scanC_ln(
    const float* __restrict__ x,
    const float* __restrict__ gamma,
    const float* __restrict__ beta)
{
    const int blk = blockIdx.x;          // 0..127
    const int b   = blk >> 3;
    const int s   = blk & (NSEG - 1);
    const int h   = threadIdx.x;
    const int lane = h & 31, w = h >> 5;

    const size_t base = ((size_t)b * Lseq + (size_t)s * SEGL) * Hh + h;
    const int q = (b << 9) | h;

    float c  = g_carry[s * NCH + q];
    const float gg = gamma[h];
    const float bb = beta[h];

    __shared__ float ssum[2][16], ssq[2][16];

    // prefetch step 0
    float f_n = __half2float(g_Fh[base]);
    float z_n = __half2float(g_Zh[base]);
    float r_n = __half2float(g_Rh[base]);
    float x_n = x[base];

    for (int l = 0; l < SEGL; ++l) {
        const float f = f_n, z = z_n, r = r_n, xv = x_n;
        if (l + 1 < SEGL) {
            size_t i = base + (size_t)(l + 1) * Hh;
            f_n = __half2float(g_Fh[i]);
            z_n = __half2float(g_Zh[i]);
            r_n = __half2float(g_Rh[i]);
            x_n = x[i];
        }

        c = fmaf(f, c - z, z);
        const float hw = fmaf(r, c - xv, 2.0f * xv);

        float sv = hw, sq = hw * hw;
        #pragma unroll
        for (int o = 16; o > 0; o >>= 1) {
            sv += __shfl_xor_sync(0xffffffffu, sv, o);
            sq += __shfl_xor_sync(0xffffffffu, sq, o);
        }
        const int pb = l & 1;
        if (lane == 0) { ssum[pb][w] = sv; ssq[pb][w] = sq; }
        __syncthreads();
        float S = 0.0f, SQ = 0.0f;
        #pragma unroll
        for (int k = 0; k < 16; k++) { S += ssum[pb][k]; SQ += ssq[pb][k]; }

        const float mean = S * (1.0f / 512.0f);
        const float var  = SQ * (1.0f / 512.0f) - mean * mean;
        const float rstd = rsqrtf(var + 1e-5f);

        g_X1h[base + (size_t)l * Hh] =
            __float2half((hw - mean) * rstd * gg + bb);
    }
}

// ---------------------------------------------------------------------------
// Final LayerNorm over 512: 1 block/row, 128 threads x float4.
//   g_X2(f32) -> outp(f32)
// ---------------------------------------------------------------------------
__global__ void ln512_out(const float* __restrict__ gamma,
                          const float* __restrict__ beta,
                          float* __restrict__ outp)
{
    const float* in = (const float*)g_X2;

    size_t row = blockIdx.x;
    int t = threadIdx.x;

    float4 v = ((const float4*)(in + row * Dm))[t];
    float s  = v.x + v.y + v.z + v.w;
    float sq = v.x*v.x + v.y*v.y + v.z*v.z + v.w*v.w;

    #pragma unroll
    for (int o = 16; o > 0; o >>= 1) {
        s  += __shfl_xor_sync(0xffffffffu, s,  o);
        sq += __shfl_xor_sync(0xffffffffu, sq, o);
    }
    __shared__ float ssum[4], ssq[4];
    int w = t >> 5;
    if ((t & 31) == 0) { ssum[w] = s; ssq[w] = sq; }
    __syncthreads();
    float S  = ssum[0] + ssum[1] + ssum[2] + ssum[3];
    float SQ = ssq[0] + ssq[1] + ssq[2] + ssq[3];

    float mean = S * (1.0f / 512.0f);
    float var  = SQ * (1.0f / 512.0f) - mean * mean;
    float rstd = rsqrtf(var + 1e-5f);

    float4 gg = ((const float4*)gamma)[t];
    float4 bb = ((const float4*)beta)[t];
    float4 o4;
    o4.x = (v.x - mean) * rstd * gg.x + bb.x;
    o4.y = (v.y - mean) * rstd * gg.y + bb.y;
    o4.z = (v.z - mean) * rstd * gg.z + bb.z;
    o4.w = (v.w - mean) * rstd * gg.w + bb.w;
    ((float4*)(outp + row * Dm))[t] = o4;
}

// ---------------------------------------------------------------------------
// Launch
// ---------------------------------------------------------------------------
extern "C" void kernel_launch(void* const* d_in, const int* in_sizes, int n_in,
                              void* d_out, int out_size)
{
    const float* x    = (const float*)d_in[0];
    const float* Wsru = (const float*)d_in[1];
    const float* b_f  = (const float*)d_in[2];
    const float* b_r  = (const float*)d_in[3];
    const float* ln1g = (const float*)d_in[4];
    const float* ln1b = (const float*)d_in[5];
    const float* W1   = (const float*)d_in[6];
    const float* b1   = (const float*)d_in[7];
    const float* W2   = (const float*)d_in[8];
    const float* b2   = (const float*)d_in[9];
    const float* ln2g = (const float*)d_in[10];
    const float* ln2b = (const float*)d_in[11];
    float* out = (float*)d_out;

    static bool attr_done = false;
    if (!attr_done) {
        cudaFuncSetAttribute(gemm_h<0, 3 * Hh, Dm>,
                             cudaFuncAttributeMaxDynamicSharedMemorySize, GSMEM);
        cudaFuncSetAttribute(gemm_h<1, DFF, Dm>,
                             cudaFuncAttributeMaxDynamicSharedMemorySize, GSMEM);
        cudaFuncSetAttribute(gemm_h<2, Dm, DFF>,
                             cudaFuncAttributeMaxDynamicSharedMemorySize, GSMEM);
        attr_done = true;
    }

    __half* dXh; __half* dWsru; __half* dW1; __half* dW2;
    cudaGetSymbolAddress((void**)&dXh,   g_Xh);
    cudaGetSymbolAddress((void**)&dWsru, g_Wsruh);
    cudaGetSymbolAddress((void**)&dW1,   g_W1h);
    cudaGetSymbolAddress((void**)&dW2,   g_W2h);

    // 0) fp32 -> fp16 pre-pass (x + all weights)
    {
        int n8 = (MROWS * Dm) / 8;
        f2h<<<(n8 + 255) / 256, 256>>>(x, dXh, n8);
        n8 = (Dm * 3 * Hh) / 8;
        f2h<<<(n8 + 255) / 256, 256>>>(Wsru, dWsru, n8);
        n8 = (Dm * DFF) / 8;
        f2h<<<(n8 + 255) / 256, 256>>>(W1, dW1, n8);
        n8 = (DFF * Dm) / 8;
        f2h<<<(n8 + 255) / 256, 256>>>(W2, dW2, n8);
    }

    // 1) u = x @ W_sru, fused gate sigmoids -> g_Zh/g_Fh/g_Rh
    gemm_h<0, 3 * Hh, Dm><<<dim3((3 * Hh) / BN, MROWS / BM), 256, GSMEM>>>(b_f, b_r);
    // 2) segmented recurrence: A (per-segment), B (carry chain)
    scanA<<<(NCH * NSEG) / 256, 256>>>();
    scanB<<<NCH / 256, 256>>>();
    // 3) pass C fused with LN1 -> g_X1h  (g_HW eliminated)
    scanC_ln<<<Bb * NSEG, 512>>>(x, ln1g, ln1b);
    // 4) h = gelu(x1 @ W1 + b1) -> g_H4h
    gemm_h<1, DFF, Dm><<<dim3(DFF / BN, MROWS / BM), 256, GSMEM>>>(b1, nullptr);
    // 5) x2 = x1 + h @ W2 + b2 -> g_X2
    gemm_h<2, Dm, DFF><<<dim3(Dm / BN, MROWS / BM), 256, GSMEM>>>(b2, nullptr);
    // 6) LN2 -> d_out
    ln512_out<<<MROWS, 128>>>(ln2g, ln2b, out);
}

// round 7
// speedup vs baseline: 1.1915x; 1.0121x over previous
#include <cuda_runtime.h>
#include <cuda_fp16.h>
#include <cstdint>
#include <cstddef>

// ---------------------------------------------------------------------------
// Problem constants: B=16, L=4096, D=H=512
// ---------------------------------------------------------------------------
constexpr int Bb   = 16;
constexpr int Lseq = 4096;
constexpr int Dm   = 512;
constexpr int Hh   = 512;
constexpr int MROWS = Bb * Lseq;          // 65536
constexpr int DFF  = 2048;                // 4*D
constexpr int NSEG = 8;
constexpr int SEGL = Lseq / NSEG;         // 512
constexpr int NCH  = Bb * Hh;             // 8192 scan chains

// ---------------------------------------------------------------------------
// Scratch (device globals)
// ---------------------------------------------------------------------------
__device__ __align__(16) __half g_Xh   [(size_t)MROWS * Dm];
__device__ __align__(16) __half g_Wsruh[(size_t)Dm * 3 * Hh];
__device__ __align__(16) __half g_W1h  [(size_t)Dm * DFF];
__device__ __align__(16) __half g_W2h  [(size_t)DFF * Dm];
__device__ __align__(16) __half g_Zh   [(size_t)MROWS * Hh];
__device__ __align__(16) __half g_Fh   [(size_t)MROWS * Hh];
__device__ __align__(16) __half g_Rh   [(size_t)MROWS * Hh];
__device__ __align__(16) __half g_X1h  [(size_t)MROWS * Dm];
__device__ __align__(16) __half g_H4h  [(size_t)MROWS * DFF];
__device__ __align__(16) float  g_X2   [(size_t)MROWS * Dm];
__device__ float g_cend [NCH * NSEG];
__device__ float g_pend [NCH * NSEG];

// ---------------------------------------------------------------------------
// Helpers
// ---------------------------------------------------------------------------
__device__ __forceinline__ void cp16(uint32_t dst_s, const void* src) {
    asm volatile("cp.async.cg.shared.global [%0], [%1], 16;\n" :: "r"(dst_s), "l"(src));
}
__device__ __forceinline__ void cp_commit() { asm volatile("cp.async.commit_group;\n"); }
template<int NN>
__device__ __forceinline__ void cp_wait() { asm volatile("cp.async.wait_group %0;\n" :: "n"(NN)); }

__device__ __forceinline__ void ldsm_x4(uint32_t& r0, uint32_t& r1, uint32_t& r2, uint32_t& r3,
                                        uint32_t addr) {
    asm volatile("ldmatrix.sync.aligned.m8n8.x4.shared.b16 {%0,%1,%2,%3},[%4];\n"
                 : "=r"(r0), "=r"(r1), "=r"(r2), "=r"(r3) : "r"(addr));
}
__device__ __forceinline__ void ldsm_x4t(uint32_t& r0, uint32_t& r1, uint32_t& r2, uint32_t& r3,
                                         uint32_t addr) {
    asm volatile("ldmatrix.sync.aligned.m8n8.x4.trans.shared.b16 {%0,%1,%2,%3},[%4];\n"
                 : "=r"(r0), "=r"(r1), "=r"(r2), "=r"(r3) : "r"(addr));
}
__device__ __forceinline__ void mma16(float* c, const uint32_t* a, const uint32_t* b) {
    asm volatile(
        "mma.sync.aligned.m16n8k16.row.col.f32.f16.f16.f32 "
        "{%0,%1,%2,%3},{%4,%5,%6,%7},{%8,%9},{%0,%1,%2,%3};\n"
        : "+f"(c[0]), "+f"(c[1]), "+f"(c[2]), "+f"(c[3])
        : "r"(a[0]), "r"(a[1]), "r"(a[2]), "r"(a[3]), "r"(b[0]), "r"(b[1]));
}

__device__ __forceinline__ float sigmoidf_(float v) { return 1.0f / (1.0f + expf(-v)); }
__device__ __forceinline__ float gelu_(float v) {
    return 0.5f * v * (1.0f + erff(v * 0.70710678118654752440f));
}

// ---------------------------------------------------------------------------
// fp32 -> fp16 (8 elems/thread); and a two-array variant
// ---------------------------------------------------------------------------
__global__ void f2h(const float* __restrict__ in, __half* __restrict__ out, int n8) {
    int i = blockIdx.x * blockDim.x + threadIdx.x;
    if (i >= n8) return;
    const float4* src = (const float4*)in + i * 2;
    float4 a = src[0], b = src[1];
    __half2 h[4];
    h[0] = __floats2half2_rn(a.x, a.y);
    h[1] = __floats2half2_rn(a.z, a.w);
    h[2] = __floats2half2_rn(b.x, b.y);
    h[3] = __floats2half2_rn(b.z, b.w);
    ((uint4*)out)[i] = *(uint4*)h;
}

__global__ void f2h2(const float* __restrict__ inA, __half* __restrict__ outA, int nA8,
                     const float* __restrict__ inB, __half* __restrict__ outB, int nB8) {
    int i = blockIdx.x * blockDim.x + threadIdx.x;
    const float* in; __half* out; int j;
    if (i < nA8) { in = inA; out = outA; j = i; }
    else if (i < nA8 + nB8) { in = inB; out = outB; j = i - nA8; }
    else return;
    const float4* src = (const float4*)in + j * 2;
    float4 a = src[0], b = src[1];
    __half2 h[4];
    h[0] = __floats2half2_rn(a.x, a.y);
    h[1] = __floats2half2_rn(a.z, a.w);
    h[2] = __floats2half2_rn(b.x, b.y);
    h[3] = __floats2half2_rn(b.z, b.w);
    ((uint4*)out)[j] = *(uint4*)h;
}

// ---------------------------------------------------------------------------
// fp16 GEMM (R4-proven config): C[M,N] = A[M,K] @ W[K,N], fused epilogues.
// Tile 128x128x64, 3-stage cp.async pipeline, 256 threads (2x4 warps @ 64x32),
// XOR-swizzled smem, ldmatrix fragment loads, 2 CTAs/SM.
// ---------------------------------------------------------------------------
constexpr int BM = 128, BN = 128, BK = 64;
constexpr int STG_BYTES = BM * BK * 2 + BK * BN * 2;   // 32KB
constexpr int GSMEM = 3 * STG_BYTES;                    // 96KB dynamic

__device__ __forceinline__ uint32_t aoff(int r, int c) {
    return (uint32_t)(r * 128 + ((c ^ (r & 7)) << 4));
}
__device__ __forceinline__ uint32_t boff(int k, int c) {
    return (uint32_t)(k * 256 + ((c ^ (k & 7)) << 4));
}

template<int EPI, int N, int K>
__global__ __launch_bounds__(256, 2) void gemm_h(
    const float* __restrict__ bias,
    const float* __restrict__ bias2)
{
    extern __shared__ __align__(1024) char dsm[];

    const __half* __restrict__ A =
        (EPI == 0) ? g_Xh : ((EPI == 1) ? g_X1h : g_H4h);
    const __half* __restrict__ W =
        (EPI == 0) ? g_Wsruh : ((EPI == 1) ? g_W1h : g_W2h);

    const int t    = threadIdx.x;
    const int m0   = blockIdx.y * BM;
    const int n0   = blockIdx.x * BN;
    const int lane = t & 31, wid = t >> 5;
    const int gq   = lane >> 2, tg = lane & 3;
    const int wm   = (wid >> 2) * 64;
    const int wn   = (wid & 3) * 32;

    const uint32_t sBase = (uint32_t)__cvta_generic_to_shared(dsm);

    float acc[4][4][4];
    #pragma unroll
    for (int i = 0; i < 4; i++)
        #pragma unroll
        for (int j = 0; j < 4; j++)
            #pragma unroll
            for (int r = 0; r < 4; r++) acc[i][j][r] = 0.0f;

    auto loadChunk = [&](int kt, int s) {
        const uint32_t aB = sBase + (uint32_t)s * STG_BYTES;
        const uint32_t bB = aB + BM * BK * 2;
        #pragma unroll
        for (int i = 0; i < 4; i++) {
            int idx = t + i * 256;
            int row = idx >> 3, c = idx & 7;
            cp16(aB + aoff(row, c),
                 A + (size_t)(m0 + row) * K + (size_t)kt * BK + c * 8);
        }
        #pragma unroll
        for (int i = 0; i < 4; i++) {
            int idx = t + i * 256;
            int row = idx >> 4, c = idx & 15;
            cp16(bB + boff(row, c),
                 W + (size_t)((size_t)kt * BK + row) * N + n0 + c * 8);
        }
        cp_commit();
    };

    const int KT = K / BK;
    loadChunk(0, 0);
    if (KT > 1) loadChunk(1, 1);

    const int ltile = lane >> 3;
    const int lrow  = lane & 7;

    for (int kt = 0; kt < KT; ++kt) {
        if (kt + 2 <= KT) cp_wait<1>(); else cp_wait<0>();
        __syncthreads();
        if (kt + 2 < KT) loadChunk(kt + 2, (kt + 2) % 3);

        const uint32_t aBase = sBase + (uint32_t)((kt % 3) * STG_BYTES);
        const uint32_t bBase = aBase + BM * BK * 2;

        #pragma unroll
        for (int ks = 0; ks < 4; ++ks) {
            uint32_t af[4][4], bf[4][2];
            #pragma unroll
            for (int mi = 0; mi < 4; mi++) {
                int row = wm + mi * 16 + ((ltile & 1) << 3) + lrow;
                int c   = ks * 2 + (ltile >> 1);
                ldsm_x4(af[mi][0], af[mi][1], af[mi][2], af[mi][3],
                        aBase + aoff(row, c));
            }
            #pragma unroll
            for (int ni2 = 0; ni2 < 2; ni2++) {
                int k = ks * 16 + ((ltile & 1) << 3) + lrow;
                int c = (wn >> 3) + ni2 * 2 + (ltile >> 1);
                uint32_t r0, r1, r2, r3;
                ldsm_x4t(r0, r1, r2, r3, bBase + boff(k, c));
                bf[ni2 * 2 + 0][0] = r0; bf[ni2 * 2 + 0][1] = r1;
                bf[ni2 * 2 + 1][0] = r2; bf[ni2 * 2 + 1][1] = r3;
            }
            #pragma unroll
            for (int mi = 0; mi < 4; mi++)
                #pragma unroll
                for (int ni = 0; ni < 4; ni++)
                    mma16(acc[mi][ni], af[mi], bf[ni]);
        }
    }

    #pragma unroll
    for (int mi = 0; mi < 4; mi++) {
        #pragma unroll
        for (int ni = 0; ni < 4; ni++) {
            #pragma unroll
            for (int half = 0; half < 2; half++) {
                int row = m0 + wm + mi * 16 + gq + half * 8;
                int col = n0 + wn + ni * 8 + tg * 2;
                float v0 = acc[mi][ni][half * 2 + 0];
                float v1 = acc[mi][ni][half * 2 + 1];
                size_t rw = (size_t)row;
                if (EPI == 0) {
                    if (col < Hh) {
                        *(__half2*)(g_Zh + rw * Hh + col) = __floats2half2_rn(v0, v1);
                    } else if (col < 2 * Hh) {
                        int h = col - Hh;
                        *(__half2*)(g_Fh + rw * Hh + h) = __floats2half2_rn(
                            sigmoidf_(v0 + bias[h]), sigmoidf_(v1 + bias[h + 1]));
                    } else {
                        int h = col - 2 * Hh;
                        *(__half2*)(g_Rh + rw * Hh + h) = __floats2half2_rn(
                            sigmoidf_(v0 + bias2[h]), sigmoidf_(v1 + bias2[h + 1]));
                    }
                } else if (EPI == 1) {
                    *(__half2*)(g_H4h + rw * N + col) = __floats2half2_rn(
                        gelu_(v0 + bias[col]), gelu_(v1 + bias[col + 1]));
                } else {
                    __half2 x1 = *(const __half2*)(g_X1h + rw * N + col);
                    float2 o;
                    o.x = v0 + bias[col]     + __half2float(__low2half(x1));
                    o.y = v1 + bias[col + 1] + __half2float(__high2half(x1));
                    *(float2*)(g_X2 + rw * N + col) = o;
                }
            }
        }
    }
}

// ---------------------------------------------------------------------------
// Segmented SRU scan, pass A: per-(b,h,seg) local scan -> (c_end, prod_f)
// ---------------------------------------------------------------------------
__global__ void scanA()
{
    int t = blockIdx.x * blockDim.x + threadIdx.x;   // 0..65535
    int q = t & (NCH - 1);
    int s = t >> 13;
    int b = q >> 9;
    int h = q & (Hh - 1);
    size_t base = ((size_t)b * Lseq + (size_t)s * SEGL) * Hh + h;

    float c = 0.0f, p = 1.0f;
    #pragma unroll 8
    for (int l = 0; l < SEGL; ++l) {
        size_t i = base + (size_t)l * Hh;
        float f = __half2float(g_Fh[i]);
        float z = __half2float(g_Zh[i]);
        c = fmaf(f, c - z, z);
        p *= f;
    }
    g_cend[t] = c;
    g_pend[t] = p;
}

// ---------------------------------------------------------------------------
// Pass C fused with LayerNorm1 (carry chain computed inline; scanB removed).
// Block = (b, seg): 512 threads, one per h.
// ---------------------------------------------------------------------------
__global__ __launch_bounds__(512, 1) void scanC_ln(
    const float* __restrict__ x,
    const float* __restrict__ gamma,
    const float* __restrict__ beta)
{
    const int blk = blockIdx.x;          // 0..127
    const int b   = blk >> 3;
    const int s   = blk & (NSEG - 1);
    const int h   = threadIdx.x;
    const int lane = h & 31, w = h >> 5;

    const size_t base = ((size_t)b * Lseq + (size_t)s * SEGL) * Hh + h;
    const int q = (b << 9) | h;

    // carry over earlier segments (<= 7 iterations)
    float c = 0.0f;
    for (int sp = 0; sp < s; ++sp) {
        int idx = sp * NCH + q;
        c = fmaf(g_pend[idx], c, g_cend[idx]);
    }

    const float gg = gamma[h];
    const float bb = beta[h];

    __shared__ float ssum[2][16], ssq[2][16];

    // prefetch step 0
    float f_n = __half2float(g_Fh[base]);
    float z_n = __half2float(g_Zh[base]);
    float r_n = __half2float(g_Rh[base]);
    float x_n = x[base];

    for (int l = 0; l < SEGL; ++l) {
        const float f = f_n, z = z_n, r = r_n, xv = x_n;
        if (l + 1 < SEGL) {
            size_t i = base + (size_t)(l + 1) * Hh;
            f_n = __half2float(g_Fh[i]);
            z_n = __half2float(g_Zh[i]);
            r_n = __half2float(g_Rh[i]);
            x_n = x[i];
        }

        c = fmaf(f, c - z, z);
        const float hw = fmaf(r, c - xv, 2.0f * xv);

        float sv = hw, sq = hw * hw;
        #pragma unroll
        for (int o = 16; o > 0; o >>= 1) {
            sv += __shfl_xor_sync(0xffffffffu, sv, o);
            sq += __shfl_xor_sync(0xffffffffu, sq, o);
        }
        const int pb = l & 1;
        if (lane == 0) { ssum[pb][w] = sv; ssq[pb][w] = sq; }
        __syncthreads();
        float S = 0.0f, SQ = 0.0f;
        #pragma unroll
        for (int k = 0; k < 16; k++) { S += ssum[pb][k]; SQ += ssq[pb][k]; }

        const float mean = S * (1.0f / 512.0f);
        const float var  = SQ * (1.0f / 512.0f) - mean * mean;
        const float rstd = rsqrtf(var + 1e-5f);

        g_X1h[base + (size_t)l * Hh] =
            __float2half((hw - mean) * rstd * gg + bb);
    }
}

// ---------------------------------------------------------------------------
// Final LayerNorm over 512: 1 block/row, 128 threads x float4.
// ---------------------------------------------------------------------------
__global__ void ln512_out(const float* __restrict__ gamma,
                          const float* __restrict__ beta,
                          float* __restrict__ outp)
{
    const float* in = (const float*)g_X2;

    size_t row = blockIdx.x;
    int t = threadIdx.x;

    float4 v = ((const float4*)(in + row * Dm))[t];
    float s  = v.x + v.y + v.z + v.w;
    float sq = v.x*v.x + v.y*v.y + v.z*v.z + v.w*v.w;

    #pragma unroll
    for (int o = 16; o > 0; o >>= 1) {
        s  += __shfl_xor_sync(0xffffffffu, s,  o);
        sq += __shfl_xor_sync(0xffffffffu, sq, o);
    }
    __shared__ float ssum[4], ssq[4];
    int w = t >> 5;
    if ((t & 31) == 0) { ssum[w] = s; ssq[w] = sq; }
    __syncthreads();
    float S  = ssum[0] + ssum[1] + ssum[2] + ssum[3];
    float SQ = ssq[0] + ssq[1] + ssq[2] + ssq[3];

    float mean = S * (1.0f / 512.0f);
    float var  = SQ * (1.0f / 512.0f) - mean * mean;
    float rstd = rsqrtf(var + 1e-5f);

    float4 gg = ((const float4*)gamma)[t];
    float4 bb = ((const float4*)beta)[t];
    float4 o4;
    o4.x = (v.x - mean) * rstd * gg.x + bb.x;
    o4.y = (v.y - mean) * rstd * gg.y + bb.y;
    o4.z = (v.z - mean) * rstd * gg.z + bb.z;
    o4.w = (v.w - mean) * rstd * gg.w + bb.w;
    ((float4*)(outp + row * Dm))[t] = o4;
}

// ---------------------------------------------------------------------------
// Launch.  Order chosen so that ncu's capture slot (our launch index 3,
// after the two harness launches with -s 5) lands on gemm_h<0>.
// ---------------------------------------------------------------------------
extern "C" void kernel_launch(void* const* d_in, const int* in_sizes, int n_in,
                              void* d_out, int out_size)
{
    const float* x    = (const float*)d_in[0];
    const float* Wsru = (const float*)d_in[1];
    const float* b_f  = (const float*)d_in[2];
    const float* b_r  = (const float*)d_in[3];
    const float* ln1g = (const float*)d_in[4];
    const float* ln1b = (const float*)d_in[5];
    const float* W1   = (const float*)d_in[6];
    const float* b1   = (const float*)d_in[7];
    const float* W2   = (const float*)d_in[8];
    const float* b2   = (const float*)d_in[9];
    const float* ln2g = (const float*)d_in[10];
    const float* ln2b = (const float*)d_in[11];
    float* out = (float*)d_out;

    static bool attr_done = false;
    if (!attr_done) {
        cudaFuncSetAttribute(gemm_h<0, 3 * Hh, Dm>,
                             cudaFuncAttributeMaxDynamicSharedMemorySize, GSMEM);
        cudaFuncSetAttribute(gemm_h<1, DFF, Dm>,
                             cudaFuncAttributeMaxDynamicSharedMemorySize, GSMEM);
        cudaFuncSetAttribute(gemm_h<2, Dm, DFF>,
                             cudaFuncAttributeMaxDynamicSharedMemorySize, GSMEM);
        attr_done = true;
    }

    __half* dXh; __half* dWsru; __half* dW1; __half* dW2;
    cudaGetSymbolAddress((void**)&dXh,   g_Xh);
    cudaGetSymbolAddress((void**)&dWsru, g_Wsruh);
    cudaGetSymbolAddress((void**)&dW1,   g_W1h);
    cudaGetSymbolAddress((void**)&dW2,   g_W2h);

    // 0) x -> fp16                                        [launch 0]
    {
        int n8 = (MROWS * Dm) / 8;
        f2h<<<(n8 + 255) / 256, 256>>>(x, dXh, n8);
    }
    // 1) Wsru -> fp16                                     [launch 1]
    {
        int n8 = (Dm * 3 * Hh) / 8;
        f2h<<<(n8 + 255) / 256, 256>>>(Wsru, dWsru, n8);
    }
    // 2) W1 + W2 -> fp16 (merged)                         [launch 2]
    {
        int nA8 = (Dm * DFF) / 8, nB8 = (DFF * Dm) / 8;
        f2h2<<<(nA8 + nB8 + 255) / 256, 256>>>(W1, dW1, nA8, W2, dW2, nB8);
    }
    // 3) u = x @ W_sru, fused gate sigmoids               [launch 3 — profiled]
    gemm_h<0, 3 * Hh, Dm><<<dim3((3 * Hh) / BN, MROWS / BM), 256, GSMEM>>>(b_f, b_r);
    // 4) segmented recurrence pass A                      [launch 4]
    scanA<<<(NCH * NSEG) / 256, 256>>>();
    // 5) pass C (inline carries) fused with LN1 -> g_X1h  [launch 5]
    scanC_ln<<<Bb * NSEG, 512>>>(x, ln1g, ln1b);
    // 6) h = gelu(x1 @ W1 + b1) -> g_H4h                  [launch 6]
    gemm_h<1, DFF, Dm><<<dim3(DFF / BN, MROWS / BM), 256, GSMEM>>>(b1, nullptr);
    // 7) x2 = x1 + h @ W2 + b2 -> g_X2                    [launch 7]
    gemm_h<2, Dm, DFF><<<dim3(Dm / BN, MROWS / BM), 256, GSMEM>>>(b2, nullptr);
    // 8) LN2 -> d_out                                     [launch 8]
    ln512_out<<<MROWS, 128>>>(ln2g, ln2b, out);
}

// round 8
// speedup vs baseline: 1.3501x; 1.1331x over previous
#include <cuda_runtime.h>
#include <cuda_fp16.h>
#include <cstdint>
#include <cstddef>

// ---------------------------------------------------------------------------
// Problem constants: B=16, L=4096, D=H=512
// ---------------------------------------------------------------------------
constexpr int Bb   = 16;
constexpr int Lseq = 4096;
constexpr int Dm   = 512;
constexpr int Hh   = 512;
constexpr int MROWS = Bb * Lseq;          // 65536
constexpr int DFF  = 2048;                // 4*D
constexpr int NSEG = 16;
constexpr int SEGL = Lseq / NSEG;         // 256
constexpr int NCH  = Bb * Hh;             // 8192 scan chains

// ---------------------------------------------------------------------------
// Scratch (device globals)
// ---------------------------------------------------------------------------
__device__ __align__(16) __half g_Xh   [(size_t)MROWS * Dm];
__device__ __align__(16) __half g_Wsruh[(size_t)Dm * 3 * Hh];
__device__ __align__(16) __half g_W1h  [(size_t)Dm * DFF];
__device__ __align__(16) __half g_W2h  [(size_t)DFF * Dm];
__device__ __align__(16) __half g_Zh   [(size_t)MROWS * Hh];
__device__ __align__(16) __half g_Fh   [(size_t)MROWS * Hh];
__device__ __align__(16) __half g_Rh   [(size_t)MROWS * Hh];
__device__ __align__(16) __half g_X1h  [(size_t)MROWS * Dm];
__device__ __align__(16) __half g_H4h  [(size_t)MROWS * DFF];
__device__ __align__(16) float  g_X2   [(size_t)MROWS * Dm];
__device__ float g_cend [NCH * NSEG];
__device__ float g_pend [NCH * NSEG];

// ---------------------------------------------------------------------------
// Helpers
// ---------------------------------------------------------------------------
__device__ __forceinline__ void cp16(uint32_t dst_s, const void* src) {
    asm volatile("cp.async.cg.shared.global [%0], [%1], 16;\n" :: "r"(dst_s), "l"(src));
}
__device__ __forceinline__ void cp_commit() { asm volatile("cp.async.commit_group;\n"); }
template<int NN>
__device__ __forceinline__ void cp_wait() { asm volatile("cp.async.wait_group %0;\n" :: "n"(NN)); }

__device__ __forceinline__ void ldsm_x4(uint32_t& r0, uint32_t& r1, uint32_t& r2, uint32_t& r3,
                                        uint32_t addr) {
    asm volatile("ldmatrix.sync.aligned.m8n8.x4.shared.b16 {%0,%1,%2,%3},[%4];\n"
                 : "=r"(r0), "=r"(r1), "=r"(r2), "=r"(r3) : "r"(addr));
}
__device__ __forceinline__ void ldsm_x4t(uint32_t& r0, uint32_t& r1, uint32_t& r2, uint32_t& r3,
                                         uint32_t addr) {
    asm volatile("ldmatrix.sync.aligned.m8n8.x4.trans.shared.b16 {%0,%1,%2,%3},[%4];\n"
                 : "=r"(r0), "=r"(r1), "=r"(r2), "=r"(r3) : "r"(addr));
}
__device__ __forceinline__ void mma16(float* c, const uint32_t* a, const uint32_t* b) {
    asm volatile(
        "mma.sync.aligned.m16n8k16.row.col.f32.f16.f16.f32 "
        "{%0,%1,%2,%3},{%4,%5,%6,%7},{%8,%9},{%0,%1,%2,%3};\n"
        : "+f"(c[0]), "+f"(c[1]), "+f"(c[2]), "+f"(c[3])
        : "r"(a[0]), "r"(a[1]), "r"(a[2]), "r"(a[3]), "r"(b[0]), "r"(b[1]));
}

__device__ __forceinline__ float sigmoidf_(float v) { return 1.0f / (1.0f + expf(-v)); }
__device__ __forceinline__ float gelu_(float v) {
    return 0.5f * v * (1.0f + erff(v * 0.70710678118654752440f));
}

// ---------------------------------------------------------------------------
// fp32 -> fp16, all four arrays in one launch
// ---------------------------------------------------------------------------
constexpr int N8_X  = (MROWS * Dm) / 8;
constexpr int N8_WS = (Dm * 3 * Hh) / 8;
constexpr int N8_W1 = (Dm * DFF) / 8;
constexpr int N8_W2 = (DFF * Dm) / 8;
constexpr int N8_TOT = N8_X + N8_WS + N8_W1 + N8_W2;

__global__ void f2h_all(const float* __restrict__ x,  const float* __restrict__ ws,
                        const float* __restrict__ w1, const float* __restrict__ w2) {
    int i = blockIdx.x * blockDim.x + threadIdx.x;
    const float* in; __half* out; int j;
    if (i < N8_X)                    { in = x;  out = g_Xh;    j = i; }
    else if (i < N8_X + N8_WS)       { in = ws; out = g_Wsruh; j = i - N8_X; }
    else if (i < N8_X + N8_WS + N8_W1) { in = w1; out = g_W1h; j = i - N8_X - N8_WS; }
    else if (i < N8_TOT)             { in = w2; out = g_W2h;   j = i - N8_X - N8_WS - N8_W1; }
    else return;
    const float4* src = (const float4*)in + (size_t)j * 2;
    float4 a = src[0], b = src[1];
    __half2 h[4];
    h[0] = __floats2half2_rn(a.x, a.y);
    h[1] = __floats2half2_rn(a.z, a.w);
    h[2] = __floats2half2_rn(b.x, b.y);
    h[3] = __floats2half2_rn(b.z, b.w);
    ((uint4*)out)[j] = *(uint4*)h;
}

// ---------------------------------------------------------------------------
// fp16 GEMM: C[M,N] = A[M,K] @ W[K,N], fused epilogues.
// Tile 128x128x64, 3-stage cp.async pipeline, 256 threads (2x4 warps @ 64x32),
// XOR-swizzled smem, ldmatrix, 2 CTAs/SM.  kt loop unrolled x6 so stage
// indices are compile-time in each unrolled body (kills %3 + address ALU).
// ---------------------------------------------------------------------------
constexpr int BM = 128, BN = 128, BK = 64;
constexpr int STG_BYTES = BM * BK * 2 + BK * BN * 2;   // 32KB
constexpr int GSMEM = 3 * STG_BYTES;                    // 96KB dynamic

__device__ __forceinline__ uint32_t aoff(int r, int c) {
    return (uint32_t)(r * 128 + ((c ^ (r & 7)) << 4));
}
__device__ __forceinline__ uint32_t boff(int k, int c) {
    return (uint32_t)(k * 256 + ((c ^ (k & 7)) << 4));
}

template<int EPI, int N, int K>
__global__ __launch_bounds__(256, 2) void gemm_h(
    const float* __restrict__ bias,
    const float* __restrict__ bias2)
{
    extern __shared__ __align__(1024) char dsm[];

    const __half* __restrict__ A =
        (EPI == 0) ? g_Xh : ((EPI == 1) ? g_X1h : g_H4h);
    const __half* __restrict__ W =
        (EPI == 0) ? g_Wsruh : ((EPI == 1) ? g_W1h : g_W2h);

    const int t    = threadIdx.x;
    const int m0   = blockIdx.y * BM;
    const int n0   = blockIdx.x * BN;
    const int lane = t & 31, wid = t >> 5;
    const int gq   = lane >> 2, tg = lane & 3;
    const int wm   = (wid >> 2) * 64;
    const int wn   = (wid & 3) * 32;

    const uint32_t sBase = (uint32_t)__cvta_generic_to_shared(dsm);

    float acc[4][4][4];
    #pragma unroll
    for (int i = 0; i < 4; i++)
        #pragma unroll
        for (int j = 0; j < 4; j++)
            #pragma unroll
            for (int r = 0; r < 4; r++) acc[i][j][r] = 0.0f;

    auto loadChunk = [&](int kt, uint32_t aB) {
        const uint32_t bB = aB + BM * BK * 2;
        #pragma unroll
        for (int i = 0; i < 4; i++) {
            int idx = t + i * 256;
            int row = idx >> 3, c = idx & 7;
            cp16(aB + aoff(row, c),
                 A + (size_t)(m0 + row) * K + (size_t)kt * BK + c * 8);
        }
        #pragma unroll
        for (int i = 0; i < 4; i++) {
            int idx = t + i * 256;
            int row = idx >> 4, c = idx & 15;
            cp16(bB + boff(row, c),
                 W + (size_t)((size_t)kt * BK + row) * N + n0 + c * 8);
        }
        cp_commit();
    };

    const int KT = K / BK;
    loadChunk(0, sBase);
    if (KT > 1) loadChunk(1, sBase + STG_BYTES);

    const int ltile = lane >> 3;
    const int lrow  = lane & 7;

    // rotating stage bases (no % in the loop)
    uint32_t stg0 = sBase, stg1 = sBase + STG_BYTES, stg2 = sBase + 2u * STG_BYTES;

    #pragma unroll 6
    for (int kt = 0; kt < KT; ++kt) {
        if (kt + 2 <= KT) cp_wait<1>(); else cp_wait<0>();
        __syncthreads();
        if (kt + 2 < KT) loadChunk(kt + 2, stg2);

        const uint32_t aBase = stg0;
        const uint32_t bBase = stg0 + BM * BK * 2;

        #pragma unroll
        for (int ks = 0; ks < 4; ++ks) {
            uint32_t af[4][4], bf[4][2];
            #pragma unroll
            for (int mi = 0; mi < 4; mi++) {
                int row = wm + mi * 16 + ((ltile & 1) << 3) + lrow;
                int c   = ks * 2 + (ltile >> 1);
                ldsm_x4(af[mi][0], af[mi][1], af[mi][2], af[mi][3],
                        aBase + aoff(row, c));
            }
            #pragma unroll
            for (int ni2 = 0; ni2 < 2; ni2++) {
                int k = ks * 16 + ((ltile & 1) << 3) + lrow;
                int c = (wn >> 3) + ni2 * 2 + (ltile >> 1);
                uint32_t r0, r1, r2, r3;
                ldsm_x4t(r0, r1, r2, r3, bBase + boff(k, c));
                bf[ni2 * 2 + 0][0] = r0; bf[ni2 * 2 + 0][1] = r1;
                bf[ni2 * 2 + 1][0] = r2; bf[ni2 * 2 + 1][1] = r3;
            }
            #pragma unroll
            for (int mi = 0; mi < 4; mi++)
                #pragma unroll
                for (int ni = 0; ni < 4; ni++)
                    mma16(acc[mi][ni], af[mi], bf[ni]);
        }

        uint32_t tmp = stg0; stg0 = stg1; stg1 = stg2; stg2 = tmp;
    }

    #pragma unroll
    for (int mi = 0; mi < 4; mi++) {
        #pragma unroll
        for (int ni = 0; ni < 4; ni++) {
            #pragma unroll
            for (int half = 0; half < 2; half++) {
                int row = m0 + wm + mi * 16 + gq + half * 8;
                int col = n0 + wn + ni * 8 + tg * 2;
                float v0 = acc[mi][ni][half * 2 + 0];
                float v1 = acc[mi][ni][half * 2 + 1];
                size_t rw = (size_t)row;
                if (EPI == 0) {
                    if (col < Hh) {
                        *(__half2*)(g_Zh + rw * Hh + col) = __floats2half2_rn(v0, v1);
                    } else if (col < 2 * Hh) {
                        int h = col - Hh;
                        *(__half2*)(g_Fh + rw * Hh + h) = __floats2half2_rn(
                            sigmoidf_(v0 + bias[h]), sigmoidf_(v1 + bias[h + 1]));
                    } else {
                        int h = col - 2 * Hh;
                        *(__half2*)(g_Rh + rw * Hh + h) = __floats2half2_rn(
                            sigmoidf_(v0 + bias2[h]), sigmoidf_(v1 + bias2[h + 1]));
                    }
                } else if (EPI == 1) {
                    *(__half2*)(g_H4h + rw * N + col) = __floats2half2_rn(
                        gelu_(v0 + bias[col]), gelu_(v1 + bias[col + 1]));
                } else {
                    __half2 x1 = *(const __half2*)(g_X1h + rw * N + col);
                    float2 o;
                    o.x = v0 + bias[col]     + __half2float(__low2half(x1));
                    o.y = v1 + bias[col + 1] + __half2float(__high2half(x1));
                    *(float2*)(g_X2 + rw * N + col) = o;
                }
            }
        }
    }
}

// ---------------------------------------------------------------------------
// Segmented SRU scan, pass A: per-(b,h,seg) local scan -> (c_end, prod_f)
// ---------------------------------------------------------------------------
__global__ void scanA()
{
    int t = blockIdx.x * blockDim.x + threadIdx.x;   // 0..NCH*NSEG-1
    int q = t & (NCH - 1);
    int s = t >> 13;
    int b = q >> 9;
    int h = q & (Hh - 1);
    size_t base = ((size_t)b * Lseq + (size_t)s * SEGL) * Hh + h;

    float c = 0.0f, p = 1.0f;
    #pragma unroll 8
    for (int l = 0; l < SEGL; ++l) {
        size_t i = base + (size_t)l * Hh;
        float f = __half2float(g_Fh[i]);
        float z = __half2float(g_Zh[i]);
        c = fmaf(f, c - z, z);
        p *= f;
    }
    g_cend[t] = c;
    g_pend[t] = p;
}

// ---------------------------------------------------------------------------
// Pass C fused with LayerNorm1 (carries inline).  Block = (b, seg):
// 512 threads, one per h; walks SEGL timesteps.
// ---------------------------------------------------------------------------
__global__ __launch_bounds__(512, 2) void scanC_ln(
    const float* __restrict__ x,
    const float* __restrict__ gamma,
    const float* __restrict__ beta)
{
    const int blk = blockIdx.x;          // 0..Bb*NSEG-1
    const int b   = blk >> 4;
    const int s   = blk & (NSEG - 1);
    const int h   = threadIdx.x;
    const int lane = h & 31, w = h >> 5;

    const size_t base = ((size_t)b * Lseq + (size_t)s * SEGL) * Hh + h;
    const int q = (b << 9) | h;

    // carry over earlier segments (<= 15 iterations)
    float c = 0.0f;
    for (int sp = 0; sp < s; ++sp) {
        int idx = sp * NCH + q;
        c = fmaf(g_pend[idx], c, g_cend[idx]);
    }

    const float gg = gamma[h];
    const float bb = beta[h];

    __shared__ float ssum[2][16], ssq[2][16];

    // prefetch step 0
    float f_n = __half2float(g_Fh[base]);
    float z_n = __half2float(g_Zh[base]);
    float r_n = __half2float(g_Rh[base]);
    float x_n = x[base];

    for (int l = 0; l < SEGL; ++l) {
        const float f = f_n, z = z_n, r = r_n, xv = x_n;
        if (l + 1 < SEGL) {
            size_t i = base + (size_t)(l + 1) * Hh;
            f_n = __half2float(g_Fh[i]);
            z_n = __half2float(g_Zh[i]);
            r_n = __half2float(g_Rh[i]);
            x_n = x[i];
        }

        c = fmaf(f, c - z, z);
        const float hw = fmaf(r, c - xv, 2.0f * xv);

        float sv = hw, sq = hw * hw;
        #pragma unroll
        for (int o = 16; o > 0; o >>= 1) {
            sv += __shfl_xor_sync(0xffffffffu, sv, o);
            sq += __shfl_xor_sync(0xffffffffu, sq, o);
        }
        const int pb = l & 1;
        if (lane == 0) { ssum[pb][w] = sv; ssq[pb][w] = sq; }
        __syncthreads();
        float S = 0.0f, SQ = 0.0f;
        #pragma unroll
        for (int k = 0; k < 16; k++) { S += ssum[pb][k]; SQ += ssq[pb][k]; }

        const float mean = S * (1.0f / 512.0f);
        const float var  = SQ * (1.0f / 512.0f) - mean * mean;
        const float rstd = rsqrtf(var + 1e-5f);

        g_X1h[base + (size_t)l * Hh] =
            __float2half((hw - mean) * rstd * gg + bb);
    }
}

// ---------------------------------------------------------------------------
// Final LayerNorm over 512: 1 block/row, 128 threads x float4.
// ---------------------------------------------------------------------------
__global__ void ln512_out(const float* __restrict__ gamma,
                          const float* __restrict__ beta,
                          float* __restrict__ outp)
{
    const float* in = (const float*)g_X2;

    size_t row = blockIdx.x;
    int t = threadIdx.x;

    float4 v = ((const float4*)(in + row * Dm))[t];
    float s  = v.x + v.y + v.z + v.w;
    float sq = v.x*v.x + v.y*v.y + v.z*v.z + v.w*v.w;

    #pragma unroll
    for (int o = 16; o > 0; o >>= 1) {
        s  += __shfl_xor_sync(0xffffffffu, s,  o);
        sq += __shfl_xor_sync(0xffffffffu, sq, o);
    }
    __shared__ float ssum[4], ssq[4];
    int w = t >> 5;
    if ((t & 31) == 0) { ssum[w] = s; ssq[w] = sq; }
    __syncthreads();
    float S  = ssum[0] + ssum[1] + ssum[2] + ssum[3];
    float SQ = ssq[0] + ssq[1] + ssq[2] + ssq[3];

    float mean = S * (1.0f / 512.0f);
    float var  = SQ * (1.0f / 512.0f) - mean * mean;
    float rstd = rsqrtf(var + 1e-5f);

    float4 gg = ((const float4*)gamma)[t];
    float4 bb = ((const float4*)beta)[t];
    float4 o4;
    o4.x = (v.x - mean) * rstd * gg.x + bb.x;
    o4.y = (v.y - mean) * rstd * gg.y + bb.y;
    o4.z = (v.z - mean) * rstd * gg.z + bb.z;
    o4.w = (v.w - mean) * rstd * gg.w + bb.w;
    ((float4*)(outp + row * Dm))[t] = o4;
}

// ---------------------------------------------------------------------------
// Launch.  ncu capture slot (our launch index 3, -s 5 minus two harness
// launches) must stay on a GEMM: order = f2h_all, scanA-placeholder... keep
// gemm_h<0> at index 1?  Capture proved to land on our 4th launch; with
// f2h_all at 0, gemm<0> at 1, scanA at 2, scanC at 3 we'd profile scanC.
// Keep a dummy split so gemm_h<1> (the biggest GEMM) is index 3.
// ---------------------------------------------------------------------------
extern "C" void kernel_launch(void* const* d_in, const int* in_sizes, int n_in,
                              void* d_out, int out_size)
{
    const float* x    = (const float*)d_in[0];
    const float* Wsru = (const float*)d_in[1];
    const float* b_f  = (const float*)d_in[2];
    const float* b_r  = (const float*)d_in[3];
    const float* ln1g = (const float*)d_in[4];
    const float* ln1b = (const float*)d_in[5];
    const float* W1   = (const float*)d_in[6];
    const float* b1   = (const float*)d_in[7];
    const float* W2   = (const float*)d_in[8];
    const float* b2   = (const float*)d_in[9];
    const float* ln2g = (const float*)d_in[10];
    const float* ln2b = (const float*)d_in[11];
    float* out = (float*)d_out;

    static bool attr_done = false;
    if (!attr_done) {
        cudaFuncSetAttribute(gemm_h<0, 3 * Hh, Dm>,
                             cudaFuncAttributeMaxDynamicSharedMemorySize, GSMEM);
        cudaFuncSetAttribute(gemm_h<1, DFF, Dm>,
                             cudaFuncAttributeMaxDynamicSharedMemorySize, GSMEM);
        cudaFuncSetAttribute(gemm_h<2, Dm, DFF>,
                             cudaFuncAttributeMaxDynamicSharedMemorySize, GSMEM);
        attr_done = true;
    }

    // 0) all fp32 -> fp16 conversions                       [launch 0]
    f2h_all<<<(N8_TOT + 255) / 256, 256>>>(x, Wsru, W1, W2);
    // 1) u = x @ W_sru, fused gate sigmoids                 [launch 1]
    gemm_h<0, 3 * Hh, Dm><<<dim3((3 * Hh) / BN, MROWS / BM), 256, GSMEM>>>(b_f, b_r);
    // 2) segmented recurrence pass A                        [launch 2]
    scanA<<<(NCH * NSEG) / 256, 256>>>();
    // 3) pass C (inline carries) fused with LN1 -> g_X1h    [launch 3 — profiled]
    scanC_ln<<<Bb * NSEG, 512>>>(x, ln1g, ln1b);
    // 4) h = gelu(x1 @ W1 + b1) -> g_H4h                    [launch 4]
    gemm_h<1, DFF, Dm><<<dim3(DFF / BN, MROWS / BM), 256, GSMEM>>>(b1, nullptr);
    // 5) x2 = x1 + h @ W2 + b2 -> g_X2                      [launch 5]
    gemm_h<2, Dm, DFF><<<dim3(Dm / BN, MROWS / BM), 256, GSMEM>>>(b2, nullptr);
    // 6) LN2 -> d_out                                       [launch 6]
    ln512_out<<<MROWS, 128>>>(ln2g, ln2b, out);
}

// round 9
// speedup vs baseline: 1.4183x; 1.0505x over previous
#include <cuda_runtime.h>
#include <cuda_fp16.h>
#include <cstdint>
#include <cstddef>

// ---------------------------------------------------------------------------
// Problem constants: B=16, L=4096, D=H=512
// ---------------------------------------------------------------------------
constexpr int Bb   = 16;
constexpr int Lseq = 4096;
constexpr int Dm   = 512;
constexpr int Hh   = 512;
constexpr int MROWS = Bb * Lseq;          // 65536
constexpr int DFF  = 2048;                // 4*D
constexpr int NSEG = 32;
constexpr int SEGL = Lseq / NSEG;         // 128
constexpr int NCH  = Bb * Hh;             // 8192 scan chains

// ---------------------------------------------------------------------------
// Scratch (device globals)
// ---------------------------------------------------------------------------
__device__ __align__(16) __half g_Xh   [(size_t)MROWS * Dm];
__device__ __align__(16) __half g_Wsruh[(size_t)Dm * 3 * Hh];
__device__ __align__(16) __half g_W1h  [(size_t)Dm * DFF];
__device__ __align__(16) __half g_W2h  [(size_t)DFF * Dm];
__device__ __align__(16) __half g_Zh   [(size_t)MROWS * Hh];
__device__ __align__(16) __half g_Fh   [(size_t)MROWS * Hh];
__device__ __align__(16) __half g_Rh   [(size_t)MROWS * Hh];
__device__ __align__(16) __half g_X1h  [(size_t)MROWS * Dm];
__device__ __align__(16) __half g_H4h  [(size_t)MROWS * DFF];
__device__ __align__(16) float  g_X2   [(size_t)MROWS * Dm];
__device__ __align__(16) float  g_cend [NCH * NSEG];
__device__ __align__(16) float  g_pend [NCH * NSEG];

// ---------------------------------------------------------------------------
// Helpers
// ---------------------------------------------------------------------------
__device__ __forceinline__ void cp16(uint32_t dst_s, const void* src) {
    asm volatile("cp.async.cg.shared.global [%0], [%1], 16;\n" :: "r"(dst_s), "l"(src));
}
__device__ __forceinline__ void cp_commit() { asm volatile("cp.async.commit_group;\n"); }
template<int NN>
__device__ __forceinline__ void cp_wait() { asm volatile("cp.async.wait_group %0;\n" :: "n"(NN)); }

__device__ __forceinline__ void ldsm_x4(uint32_t& r0, uint32_t& r1, uint32_t& r2, uint32_t& r3,
                                        uint32_t addr) {
    asm volatile("ldmatrix.sync.aligned.m8n8.x4.shared.b16 {%0,%1,%2,%3},[%4];\n"
                 : "=r"(r0), "=r"(r1), "=r"(r2), "=r"(r3) : "r"(addr));
}
__device__ __forceinline__ void ldsm_x4t(uint32_t& r0, uint32_t& r1, uint32_t& r2, uint32_t& r3,
                                         uint32_t addr) {
    asm volatile("ldmatrix.sync.aligned.m8n8.x4.trans.shared.b16 {%0,%1,%2,%3},[%4];\n"
                 : "=r"(r0), "=r"(r1), "=r"(r2), "=r"(r3) : "r"(addr));
}
__device__ __forceinline__ void mma16(float* c, const uint32_t* a, const uint32_t* b) {
    asm volatile(
        "mma.sync.aligned.m16n8k16.row.col.f32.f16.f16.f32 "
        "{%0,%1,%2,%3},{%4,%5,%6,%7},{%8,%9},{%0,%1,%2,%3};\n"
        : "+f"(c[0]), "+f"(c[1]), "+f"(c[2]), "+f"(c[3])
        : "r"(a[0]), "r"(a[1]), "r"(a[2]), "r"(a[3]), "r"(b[0]), "r"(b[1]));
}

__device__ __forceinline__ float sigmoidf_(float v) { return 1.0f / (1.0f + expf(-v)); }
__device__ __forceinline__ float gelu_(float v) {
    return 0.5f * v * (1.0f + erff(v * 0.70710678118654752440f));
}

// ---------------------------------------------------------------------------
// fp32 -> fp16, all four arrays in one launch
// ---------------------------------------------------------------------------
constexpr int N8_X  = (MROWS * Dm) / 8;
constexpr int N8_WS = (Dm * 3 * Hh) / 8;
constexpr int N8_W1 = (Dm * DFF) / 8;
constexpr int N8_W2 = (DFF * Dm) / 8;
constexpr int N8_TOT = N8_X + N8_WS + N8_W1 + N8_W2;

__global__ void f2h_all(const float* __restrict__ x,  const float* __restrict__ ws,
                        const float* __restrict__ w1, const float* __restrict__ w2) {
    int i = blockIdx.x * blockDim.x + threadIdx.x;
    const float* in; __half* out; int j;
    if (i < N8_X)                    { in = x;  out = g_Xh;    j = i; }
    else if (i < N8_X + N8_WS)       { in = ws; out = g_Wsruh; j = i - N8_X; }
    else if (i < N8_X + N8_WS + N8_W1) { in = w1; out = g_W1h; j = i - N8_X - N8_WS; }
    else if (i < N8_TOT)             { in = w2; out = g_W2h;   j = i - N8_X - N8_WS - N8_W1; }
    else return;
    const float4* src = (const float4*)in + (size_t)j * 2;
    float4 a = src[0], b = src[1];
    __half2 h[4];
    h[0] = __floats2half2_rn(a.x, a.y);
    h[1] = __floats2half2_rn(a.z, a.w);
    h[2] = __floats2half2_rn(b.x, b.y);
    h[3] = __floats2half2_rn(b.z, b.w);
    ((uint4*)out)[j] = *(uint4*)h;
}

// ---------------------------------------------------------------------------
// fp16 GEMM (R8-proven): tile 128x128x64, 3-stage cp.async, 256 thr, 2 CTA/SM,
// kt loop unrolled x6 with rotating stage bases.
// ---------------------------------------------------------------------------
constexpr int BM = 128, BN = 128, BK = 64;
constexpr int STG_BYTES = BM * BK * 2 + BK * BN * 2;   // 32KB
constexpr int GSMEM = 3 * STG_BYTES;                    // 96KB dynamic

__device__ __forceinline__ uint32_t aoff(int r, int c) {
    return (uint32_t)(r * 128 + ((c ^ (r & 7)) << 4));
}
__device__ __forceinline__ uint32_t boff(int k, int c) {
    return (uint32_t)(k * 256 + ((c ^ (k & 7)) << 4));
}

template<int EPI, int N, int K>
__global__ __launch_bounds__(256, 2) void gemm_h(
    const float* __restrict__ bias,
    const float* __restrict__ bias2)
{
    extern __shared__ __align__(1024) char dsm[];

    const __half* __restrict__ A =
        (EPI == 0) ? g_Xh : ((EPI == 1) ? g_X1h : g_H4h);
    const __half* __restrict__ W =
        (EPI == 0) ? g_Wsruh : ((EPI == 1) ? g_W1h : g_W2h);

    const int t    = threadIdx.x;
    const int m0   = blockIdx.y * BM;
    const int n0   = blockIdx.x * BN;
    const int lane = t & 31, wid = t >> 5;
    const int gq   = lane >> 2, tg = lane & 3;
    const int wm   = (wid >> 2) * 64;
    const int wn   = (wid & 3) * 32;

    const uint32_t sBase = (uint32_t)__cvta_generic_to_shared(dsm);

    float acc[4][4][4];
    #pragma unroll
    for (int i = 0; i < 4; i++)
        #pragma unroll
        for (int j = 0; j < 4; j++)
            #pragma unroll
            for (int r = 0; r < 4; r++) acc[i][j][r] = 0.0f;

    auto loadChunk = [&](int kt, uint32_t aB) {
        const uint32_t bB = aB + BM * BK * 2;
        #pragma unroll
        for (int i = 0; i < 4; i++) {
            int idx = t + i * 256;
            int row = idx >> 3, c = idx & 7;
            cp16(aB + aoff(row, c),
                 A + (size_t)(m0 + row) * K + (size_t)kt * BK + c * 8);
        }
        #pragma unroll
        for (int i = 0; i < 4; i++) {
            int idx = t + i * 256;
            int row = idx >> 4, c = idx & 15;
            cp16(bB + boff(row, c),
                 W + (size_t)((size_t)kt * BK + row) * N + n0 + c * 8);
        }
        cp_commit();
    };

    const int KT = K / BK;
    loadChunk(0, sBase);
    if (KT > 1) loadChunk(1, sBase + STG_BYTES);

    const int ltile = lane >> 3;
    const int lrow  = lane & 7;

    uint32_t stg0 = sBase, stg1 = sBase + STG_BYTES, stg2 = sBase + 2u * STG_BYTES;

    #pragma unroll 6
    for (int kt = 0; kt < KT; ++kt) {
        if (kt + 2 <= KT) cp_wait<1>(); else cp_wait<0>();
        __syncthreads();
        if (kt + 2 < KT) loadChunk(kt + 2, stg2);

        const uint32_t aBase = stg0;
        const uint32_t bBase = stg0 + BM * BK * 2;

        #pragma unroll
        for (int ks = 0; ks < 4; ++ks) {
            uint32_t af[4][4], bf[4][2];
            #pragma unroll
            for (int mi = 0; mi < 4; mi++) {
                int row = wm + mi * 16 + ((ltile & 1) << 3) + lrow;
                int c   = ks * 2 + (ltile >> 1);
                ldsm_x4(af[mi][0], af[mi][1], af[mi][2], af[mi][3],
                        aBase + aoff(row, c));
            }
            #pragma unroll
            for (int ni2 = 0; ni2 < 2; ni2++) {
                int k = ks * 16 + ((ltile & 1) << 3) + lrow;
                int c = (wn >> 3) + ni2 * 2 + (ltile >> 1);
                uint32_t r0, r1, r2, r3;
                ldsm_x4t(r0, r1, r2, r3, bBase + boff(k, c));
                bf[ni2 * 2 + 0][0] = r0; bf[ni2 * 2 + 0][1] = r1;
                bf[ni2 * 2 + 1][0] = r2; bf[ni2 * 2 + 1][1] = r3;
            }
            #pragma unroll
            for (int mi = 0; mi < 4; mi++)
                #pragma unroll
                for (int ni = 0; ni < 4; ni++)
                    mma16(acc[mi][ni], af[mi], bf[ni]);
        }

        uint32_t tmp = stg0; stg0 = stg1; stg1 = stg2; stg2 = tmp;
    }

    #pragma unroll
    for (int mi = 0; mi < 4; mi++) {
        #pragma unroll
        for (int ni = 0; ni < 4; ni++) {
            #pragma unroll
            for (int half = 0; half < 2; half++) {
                int row = m0 + wm + mi * 16 + gq + half * 8;
                int col = n0 + wn + ni * 8 + tg * 2;
                float v0 = acc[mi][ni][half * 2 + 0];
                float v1 = acc[mi][ni][half * 2 + 1];
                size_t rw = (size_t)row;
                if (EPI == 0) {
                    if (col < Hh) {
                        *(__half2*)(g_Zh + rw * Hh + col) = __floats2half2_rn(v0, v1);
                    } else if (col < 2 * Hh) {
                        int h = col - Hh;
                        *(__half2*)(g_Fh + rw * Hh + h) = __floats2half2_rn(
                            sigmoidf_(v0 + bias[h]), sigmoidf_(v1 + bias[h + 1]));
                    } else {
                        int h = col - 2 * Hh;
                        *(__half2*)(g_Rh + rw * Hh + h) = __floats2half2_rn(
                            sigmoidf_(v0 + bias2[h]), sigmoidf_(v1 + bias2[h + 1]));
                    }
                } else if (EPI == 1) {
                    *(__half2*)(g_H4h + rw * N + col) = __floats2half2_rn(
                        gelu_(v0 + bias[col]), gelu_(v1 + bias[col + 1]));
                } else {
                    __half2 x1 = *(const __half2*)(g_X1h + rw * N + col);
                    float2 o;
                    o.x = v0 + bias[col]     + __half2float(__low2half(x1));
                    o.y = v1 + bias[col + 1] + __half2float(__high2half(x1));
                    *(float2*)(g_X2 + rw * N + col) = o;
                }
            }
        }
    }
}

// ---------------------------------------------------------------------------
// Segmented SRU scan, pass A: 4 chains/thread, uint2 (4xfp16) loads.
// ---------------------------------------------------------------------------
__global__ void scanA()
{
    int t = blockIdx.x * blockDim.x + threadIdx.x;   // 0 .. NCH*NSEG/4-1
    int qb = (t & (NCH / 4 - 1)) << 2;               // chain base (mult of 4)
    int s  = t >> 11;                                // NCH/4 = 2048
    int b  = qb >> 9;
    int h  = qb & (Hh - 1);
    size_t base = ((size_t)b * Lseq + (size_t)s * SEGL) * Hh + h;

    float c0 = 0.f, c1 = 0.f, c2 = 0.f, c3 = 0.f;
    float p0 = 1.f, p1 = 1.f, p2 = 1.f, p3 = 1.f;
    #pragma unroll 4
    for (int l = 0; l < SEGL; ++l) {
        size_t i = base + (size_t)l * Hh;
        uint2 fr = *(const uint2*)(g_Fh + i);
        uint2 zr = *(const uint2*)(g_Zh + i);
        float2 fa = __half22float2(*(__half2*)&fr.x);
        float2 fb = __half22float2(*(__half2*)&fr.y);
        float2 za = __half22float2(*(__half2*)&zr.x);
        float2 zb = __half22float2(*(__half2*)&zr.y);
        c0 = fmaf(fa.x, c0 - za.x, za.x); p0 *= fa.x;
        c1 = fmaf(fa.y, c1 - za.y, za.y); p1 *= fa.y;
        c2 = fmaf(fb.x, c2 - zb.x, zb.x); p2 *= fb.x;
        c3 = fmaf(fb.y, c3 - zb.y, zb.y); p3 *= fb.y;
    }
    int idx = s * NCH + qb;
    *(float4*)(g_cend + idx) = make_float4(c0, c1, c2, c3);
    *(float4*)(g_pend + idx) = make_float4(p0, p1, p2, p3);
}

// ---------------------------------------------------------------------------
// Pass C fused with LayerNorm1.  Block = (b, seg): 256 threads x 2 chains
// (half2/float2 vectorized).  x read from g_Xh (fp16).
// ---------------------------------------------------------------------------
__global__ __launch_bounds__(256, 2) void scanC_ln(
    const float* __restrict__ gamma,
    const float* __restrict__ beta)
{
    const int blk = blockIdx.x;          // 0..Bb*NSEG-1
    const int b   = blk >> 5;
    const int s   = blk & (NSEG - 1);
    const int tid = threadIdx.x;
    const int h0  = tid << 1;
    const int lane = tid & 31, w = tid >> 5;

    const size_t base = ((size_t)b * Lseq + (size_t)s * SEGL) * Hh + h0;
    const int q = (b << 9) | h0;

    // carry over earlier segments (<= 31 iterations, float2)
    float c0 = 0.f, c1 = 0.f;
    for (int sp = 0; sp < s; ++sp) {
        int idx = sp * NCH + q;
        float2 ce = *(const float2*)(g_cend + idx);
        float2 pe = *(const float2*)(g_pend + idx);
        c0 = fmaf(pe.x, c0, ce.x);
        c1 = fmaf(pe.y, c1, ce.y);
    }

    const float2 gg = *(const float2*)(gamma + h0);
    const float2 bb = *(const float2*)(beta  + h0);

    __shared__ float ssum[2][8], ssq[2][8];

    // prefetch step 0
    float2 f_n = __half22float2(*(const __half2*)(g_Fh + base));
    float2 z_n = __half22float2(*(const __half2*)(g_Zh + base));
    float2 r_n = __half22float2(*(const __half2*)(g_Rh + base));
    float2 x_n = __half22float2(*(const __half2*)(g_Xh + base));

    for (int l = 0; l < SEGL; ++l) {
        const float2 f = f_n, z = z_n, r = r_n, xv = x_n;
        if (l + 1 < SEGL) {
            size_t i = base + (size_t)(l + 1) * Hh;
            f_n = __half22float2(*(const __half2*)(g_Fh + i));
            z_n = __half22float2(*(const __half2*)(g_Zh + i));
            r_n = __half22float2(*(const __half2*)(g_Rh + i));
            x_n = __half22float2(*(const __half2*)(g_Xh + i));
        }

        c0 = fmaf(f.x, c0 - z.x, z.x);
        c1 = fmaf(f.y, c1 - z.y, z.y);
        const float hw0 = fmaf(r.x, c0 - xv.x, 2.0f * xv.x);
        const float hw1 = fmaf(r.y, c1 - xv.y, 2.0f * xv.y);

        float sv = hw0 + hw1;
        float sq = fmaf(hw0, hw0, hw1 * hw1);
        #pragma unroll
        for (int o = 16; o > 0; o >>= 1) {
            sv += __shfl_xor_sync(0xffffffffu, sv, o);
            sq += __shfl_xor_sync(0xffffffffu, sq, o);
        }
        const int pb = l & 1;
        if (lane == 0) { ssum[pb][w] = sv; ssq[pb][w] = sq; }
        __syncthreads();
        float S = 0.0f, SQ = 0.0f;
        #pragma unroll
        for (int k = 0; k < 8; k++) { S += ssum[pb][k]; SQ += ssq[pb][k]; }

        const float mean = S * (1.0f / 512.0f);
        const float var  = SQ * (1.0f / 512.0f) - mean * mean;
        const float rstd = rsqrtf(var + 1e-5f);

        *(__half2*)(g_X1h + base + (size_t)l * Hh) = __floats2half2_rn(
            (hw0 - mean) * rstd * gg.x + bb.x,
            (hw1 - mean) * rstd * gg.y + bb.y);
    }
}

// ---------------------------------------------------------------------------
// Final LayerNorm over 512: 1 block/row, 128 threads x float4.
// ---------------------------------------------------------------------------
__global__ void ln512_out(const float* __restrict__ gamma,
                          const float* __restrict__ beta,
                          float* __restrict__ outp)
{
    const float* in = (const float*)g_X2;

    size_t row = blockIdx.x;
    int t = threadIdx.x;

    float4 v = ((const float4*)(in + row * Dm))[t];
    float s  = v.x + v.y + v.z + v.w;
    float sq = v.x*v.x + v.y*v.y + v.z*v.z + v.w*v.w;

    #pragma unroll
    for (int o = 16; o > 0; o >>= 1) {
        s  += __shfl_xor_sync(0xffffffffu, s,  o);
        sq += __shfl_xor_sync(0xffffffffu, sq, o);
    }
    __shared__ float ssum[4], ssq[4];
    int w = t >> 5;
    if ((t & 31) == 0) { ssum[w] = s; ssq[w] = sq; }
    __syncthreads();
    float S  = ssum[0] + ssum[1] + ssum[2] + ssum[3];
    float SQ = ssq[0] + ssq[1] + ssq[2] + ssq[3];

    float mean = S * (1.0f / 512.0f);
    float var  = SQ * (1.0f / 512.0f) - mean * mean;
    float rstd = rsqrtf(var + 1e-5f);

    float4 gg = ((const float4*)gamma)[t];
    float4 bb = ((const float4*)beta)[t];
    float4 o4;
    o4.x = (v.x - mean) * rstd * gg.x + bb.x;
    o4.y = (v.y - mean) * rstd * gg.y + bb.y;
    o4.z = (v.z - mean) * rstd * gg.z + bb.z;
    o4.w = (v.w - mean) * rstd * gg.w + bb.w;
    ((float4*)(outp + row * Dm))[t] = o4;
}

// ---------------------------------------------------------------------------
// Launch.  scanC_ln stays at profiled slot (our launch index 3).
// ---------------------------------------------------------------------------
extern "C" void kernel_launch(void* const* d_in, const int* in_sizes, int n_in,
                              void* d_out, int out_size)
{
    const float* x    = (const float*)d_in[0];
    const float* Wsru = (const float*)d_in[1];
    const float* b_f  = (const float*)d_in[2];
    const float* b_r  = (const float*)d_in[3];
    const float* ln1g = (const float*)d_in[4];
    const float* ln1b = (const float*)d_in[5];
    const float* W1   = (const float*)d_in[6];
    const float* b1   = (const float*)d_in[7];
    const float* W2   = (const float*)d_in[8];
    const float* b2   = (const float*)d_in[9];
    const float* ln2g = (const float*)d_in[10];
    const float* ln2b = (const float*)d_in[11];
    float* out = (float*)d_out;

    static bool attr_done = false;
    if (!attr_done) {
        cudaFuncSetAttribute(gemm_h<0, 3 * Hh, Dm>,
                             cudaFuncAttributeMaxDynamicSharedMemorySize, GSMEM);
        cudaFuncSetAttribute(gemm_h<1, DFF, Dm>,
                             cudaFuncAttributeMaxDynamicSharedMemorySize, GSMEM);
        cudaFuncSetAttribute(gemm_h<2, Dm, DFF>,
                             cudaFuncAttributeMaxDynamicSharedMemorySize, GSMEM);
        attr_done = true;
    }

    // 0) all fp32 -> fp16 conversions                       [launch 0]
    f2h_all<<<(N8_TOT + 255) / 256, 256>>>(x, Wsru, W1, W2);
    // 1) u = x @ W_sru, fused gate sigmoids                 [launch 1]
    gemm_h<0, 3 * Hh, Dm><<<dim3((3 * Hh) / BN, MROWS / BM), 256, GSMEM>>>(b_f, b_r);
    // 2) segmented recurrence pass A                        [launch 2]
    scanA<<<(NCH * NSEG / 4) / 256, 256>>>();
    // 3) pass C (inline carries) fused with LN1 -> g_X1h    [launch 3 — profiled]
    scanC_ln<<<Bb * NSEG, 256>>>(ln1g, ln1b);
    // 4) h = gelu(x1 @ W1 + b1) -> g_H4h                    [launch 4]
    gemm_h<1, DFF, Dm><<<dim3(DFF / BN, MROWS / BM), 256, GSMEM>>>(b1, nullptr);
    // 5) x2 = x1 + h @ W2 + b2 -> g_X2                      [launch 5]
    gemm_h<2, Dm, DFF><<<dim3(Dm / BN, MROWS / BM), 256, GSMEM>>>(b2, nullptr);
    // 6) LN2 -> d_out                                       [launch 6]
    ln512_out<<<MROWS, 128>>>(ln2g, ln2b, out);
}

// round 10
// speedup vs baseline: 1.4778x; 1.0419x over previous
#include <cuda_runtime.h>
#include <cuda_fp16.h>
#include <cstdint>
#include <cstddef>

// ---------------------------------------------------------------------------
// Problem constants: B=16, L=4096, D=H=512
// ---------------------------------------------------------------------------
constexpr int Bb   = 16;
constexpr int Lseq = 4096;
constexpr int Dm   = 512;
constexpr int Hh   = 512;
constexpr int MROWS = Bb * Lseq;          // 65536
constexpr int DFF  = 2048;                // 4*D
constexpr int NSEG = 64;
constexpr int SEGL = Lseq / NSEG;         // 64
constexpr int NCH  = Bb * Hh;             // 8192 scan chains

// ---------------------------------------------------------------------------
// Scratch (device globals)
// ---------------------------------------------------------------------------
__device__ __align__(16) __half g_Xh   [(size_t)MROWS * Dm];
__device__ __align__(16) __half g_Wsruh[(size_t)Dm * 3 * Hh];
__device__ __align__(16) __half g_W1h  [(size_t)Dm * DFF];
__device__ __align__(16) __half g_W2h  [(size_t)DFF * Dm];
__device__ __align__(16) __half g_Zh   [(size_t)MROWS * Hh];
__device__ __align__(16) __half g_Fh   [(size_t)MROWS * Hh];
__device__ __align__(16) __half g_Rh   [(size_t)MROWS * Hh];
__device__ __align__(16) __half g_X1h  [(size_t)MROWS * Dm];
__device__ __align__(16) __half g_H4h  [(size_t)MROWS * DFF];
__device__ __align__(16) float  g_X2   [(size_t)MROWS * Dm];
__device__ __align__(16) float  g_cend [NCH * NSEG];
__device__ __align__(16) float  g_pend [NCH * NSEG];

// ---------------------------------------------------------------------------
// Helpers
// ---------------------------------------------------------------------------
__device__ __forceinline__ void cp16(uint32_t dst_s, const void* src) {
    asm volatile("cp.async.cg.shared.global [%0], [%1], 16;\n" :: "r"(dst_s), "l"(src));
}
__device__ __forceinline__ void cp_commit() { asm volatile("cp.async.commit_group;\n"); }
template<int NN>
__device__ __forceinline__ void cp_wait() { asm volatile("cp.async.wait_group %0;\n" :: "n"(NN)); }

__device__ __forceinline__ void ldsm_x4(uint32_t& r0, uint32_t& r1, uint32_t& r2, uint32_t& r3,
                                        uint32_t addr) {
    asm volatile("ldmatrix.sync.aligned.m8n8.x4.shared.b16 {%0,%1,%2,%3},[%4];\n"
                 : "=r"(r0), "=r"(r1), "=r"(r2), "=r"(r3) : "r"(addr));
}
__device__ __forceinline__ void ldsm_x4t(uint32_t& r0, uint32_t& r1, uint32_t& r2, uint32_t& r3,
                                         uint32_t addr) {
    asm volatile("ldmatrix.sync.aligned.m8n8.x4.trans.shared.b16 {%0,%1,%2,%3},[%4];\n"
                 : "=r"(r0), "=r"(r1), "=r"(r2), "=r"(r3) : "r"(addr));
}
__device__ __forceinline__ void mma16(float* c, const uint32_t* a, const uint32_t* b) {
    asm volatile(
        "mma.sync.aligned.m16n8k16.row.col.f32.f16.f16.f32 "
        "{%0,%1,%2,%3},{%4,%5,%6,%7},{%8,%9},{%0,%1,%2,%3};\n"
        : "+f"(c[0]), "+f"(c[1]), "+f"(c[2]), "+f"(c[3])
        : "r"(a[0]), "r"(a[1]), "r"(a[2]), "r"(a[3]), "r"(b[0]), "r"(b[1]));
}

__device__ __forceinline__ float sigmoidf_(float v) { return 1.0f / (1.0f + expf(-v)); }
__device__ __forceinline__ float gelu_(float v) {
    return 0.5f * v * (1.0f + erff(v * 0.70710678118654752440f));
}

// ---------------------------------------------------------------------------
// fp32 -> fp16, all four arrays in one launch
// ---------------------------------------------------------------------------
constexpr int N8_X  = (MROWS * Dm) / 8;
constexpr int N8_WS = (Dm * 3 * Hh) / 8;
constexpr int N8_W1 = (Dm * DFF) / 8;
constexpr int N8_W2 = (DFF * Dm) / 8;
constexpr int N8_TOT = N8_X + N8_WS + N8_W1 + N8_W2;

__global__ void f2h_all(const float* __restrict__ x,  const float* __restrict__ ws,
                        const float* __restrict__ w1, const float* __restrict__ w2) {
    int i = blockIdx.x * blockDim.x + threadIdx.x;
    const float* in; __half* out; int j;
    if (i < N8_X)                    { in = x;  out = g_Xh;    j = i; }
    else if (i < N8_X + N8_WS)       { in = ws; out = g_Wsruh; j = i - N8_X; }
    else if (i < N8_X + N8_WS + N8_W1) { in = w1; out = g_W1h; j = i - N8_X - N8_WS; }
    else if (i < N8_TOT)             { in = w2; out = g_W2h;   j = i - N8_X - N8_WS - N8_W1; }
    else return;
    const float4* src = (const float4*)in + (size_t)j * 2;
    float4 a = src[0], b = src[1];
    __half2 h[4];
    h[0] = __floats2half2_rn(a.x, a.y);
    h[1] = __floats2half2_rn(a.z, a.w);
    h[2] = __floats2half2_rn(b.x, b.y);
    h[3] = __floats2half2_rn(b.z, b.w);
    ((uint4*)out)[j] = *(uint4*)h;
}

// ---------------------------------------------------------------------------
// fp16 GEMM: tile 128x128x64, 3-stage cp.async, 256 thr, 2 CTA/SM, kt loop
// unrolled x6.  NEW: epilogues stage the CTA tile in smem (dead after
// mainloop) and emit fully-coalesced uint4/float4 global stores; the EPI=2
// residual read is coalesced too.
// ---------------------------------------------------------------------------
constexpr int BM = 128, BN = 128, BK = 64;
constexpr int STG_BYTES = BM * BK * 2 + BK * BN * 2;   // 32KB
constexpr int GSMEM = 3 * STG_BYTES;                    // 96KB dynamic

__device__ __forceinline__ uint32_t aoff(int r, int c) {
    return (uint32_t)(r * 128 + ((c ^ (r & 7)) << 4));
}
__device__ __forceinline__ uint32_t boff(int k, int c) {
    return (uint32_t)(k * 256 + ((c ^ (k & 7)) << 4));
}

template<int EPI, int N, int K>
__global__ __launch_bounds__(256, 2) void gemm_h(
    const float* __restrict__ bias,
    const float* __restrict__ bias2)
{
    extern __shared__ __align__(1024) char dsm[];

    const __half* __restrict__ A =
        (EPI == 0) ? g_Xh : ((EPI == 1) ? g_X1h : g_H4h);
    const __half* __restrict__ W =
        (EPI == 0) ? g_Wsruh : ((EPI == 1) ? g_W1h : g_W2h);

    const int t    = threadIdx.x;
    const int m0   = blockIdx.y * BM;
    const int n0   = blockIdx.x * BN;
    const int lane = t & 31, wid = t >> 5;
    const int gq   = lane >> 2, tg = lane & 3;
    const int wm   = (wid >> 2) * 64;
    const int wn   = (wid & 3) * 32;

    const uint32_t sBase = (uint32_t)__cvta_generic_to_shared(dsm);

    float acc[4][4][4];
    #pragma unroll
    for (int i = 0; i < 4; i++)
        #pragma unroll
        for (int j = 0; j < 4; j++)
            #pragma unroll
            for (int r = 0; r < 4; r++) acc[i][j][r] = 0.0f;

    auto loadChunk = [&](int kt, uint32_t aB) {
        const uint32_t bB = aB + BM * BK * 2;
        #pragma unroll
        for (int i = 0; i < 4; i++) {
            int idx = t + i * 256;
            int row = idx >> 3, c = idx & 7;
            cp16(aB + aoff(row, c),
                 A + (size_t)(m0 + row) * K + (size_t)kt * BK + c * 8);
        }
        #pragma unroll
        for (int i = 0; i < 4; i++) {
            int idx = t + i * 256;
            int row = idx >> 4, c = idx & 15;
            cp16(bB + boff(row, c),
                 W + (size_t)((size_t)kt * BK + row) * N + n0 + c * 8);
        }
        cp_commit();
    };

    const int KT = K / BK;
    loadChunk(0, sBase);
    if (KT > 1) loadChunk(1, sBase + STG_BYTES);

    const int ltile = lane >> 3;
    const int lrow  = lane & 7;

    uint32_t stg0 = sBase, stg1 = sBase + STG_BYTES, stg2 = sBase + 2u * STG_BYTES;

    #pragma unroll 6
    for (int kt = 0; kt < KT; ++kt) {
        if (kt + 2 <= KT) cp_wait<1>(); else cp_wait<0>();
        __syncthreads();
        if (kt + 2 < KT) loadChunk(kt + 2, stg2);

        const uint32_t aBase = stg0;
        const uint32_t bBase = stg0 + BM * BK * 2;

        #pragma unroll
        for (int ks = 0; ks < 4; ++ks) {
            uint32_t af[4][4], bf[4][2];
            #pragma unroll
            for (int mi = 0; mi < 4; mi++) {
                int row = wm + mi * 16 + ((ltile & 1) << 3) + lrow;
                int c   = ks * 2 + (ltile >> 1);
                ldsm_x4(af[mi][0], af[mi][1], af[mi][2], af[mi][3],
                        aBase + aoff(row, c));
            }
            #pragma unroll
            for (int ni2 = 0; ni2 < 2; ni2++) {
                int k = ks * 16 + ((ltile & 1) << 3) + lrow;
                int c = (wn >> 3) + ni2 * 2 + (ltile >> 1);
                uint32_t r0, r1, r2, r3;
                ldsm_x4t(r0, r1, r2, r3, bBase + boff(k, c));
                bf[ni2 * 2 + 0][0] = r0; bf[ni2 * 2 + 0][1] = r1;
                bf[ni2 * 2 + 1][0] = r2; bf[ni2 * 2 + 1][1] = r3;
            }
            #pragma unroll
            for (int mi = 0; mi < 4; mi++)
                #pragma unroll
                for (int ni = 0; ni < 4; ni++)
                    mma16(acc[mi][ni], af[mi], bf[ni]);
        }

        uint32_t tmp = stg0; stg0 = stg1; stg1 = stg2; stg2 = tmp;
    }

    // ---------------- staged epilogue (smem is dead: reuse it) --------------
    __syncthreads();

    if (EPI == 0) {
        const int seg = n0 >> 9;                 // tile fully in z|f|r region
        const int cb  = n0 - (seg << 9);
        const float* bp = (seg == 1) ? bias : bias2;
        __half* outp = (seg == 0) ? g_Zh : (seg == 1) ? g_Fh : g_Rh;
        __half* sh = (__half*)dsm;               // stride 136 halfs
        #pragma unroll
        for (int mi = 0; mi < 4; mi++)
            #pragma unroll
            for (int ni = 0; ni < 4; ni++)
                #pragma unroll
                for (int hf = 0; hf < 2; hf++) {
                    int row = wm + mi * 16 + gq + hf * 8;
                    int col = wn + ni * 8 + tg * 2;
                    float v0 = acc[mi][ni][hf * 2 + 0];
                    float v1 = acc[mi][ni][hf * 2 + 1];
                    if (seg != 0) {
                        v0 = sigmoidf_(v0 + bp[cb + col]);
                        v1 = sigmoidf_(v1 + bp[cb + col + 1]);
                    }
                    *(__half2*)(sh + row * 136 + col) = __floats2half2_rn(v0, v1);
                }
        __syncthreads();
        #pragma unroll
        for (int i = 0; i < 8; i++) {
            int idx = t + i * 256;
            int row = idx >> 4, c = idx & 15;
            uint4 v = *(uint4*)(sh + row * 136 + c * 8);
            *(uint4*)(outp + (size_t)(m0 + row) * Hh + cb + c * 8) = v;
        }
    } else if (EPI == 1) {
        __half* sh = (__half*)dsm;
        #pragma unroll
        for (int mi = 0; mi < 4; mi++)
            #pragma unroll
            for (int ni = 0; ni < 4; ni++)
                #pragma unroll
                for (int hf = 0; hf < 2; hf++) {
                    int row = wm + mi * 16 + gq + hf * 8;
                    int col = wn + ni * 8 + tg * 2;
                    float v0 = gelu_(acc[mi][ni][hf * 2 + 0] + bias[n0 + col]);
                    float v1 = gelu_(acc[mi][ni][hf * 2 + 1] + bias[n0 + col + 1]);
                    *(__half2*)(sh + row * 136 + col) = __floats2half2_rn(v0, v1);
                }
        __syncthreads();
        #pragma unroll
        for (int i = 0; i < 8; i++) {
            int idx = t + i * 256;
            int row = idx >> 4, c = idx & 15;
            uint4 v = *(uint4*)(sh + row * 136 + c * 8);
            *(uint4*)(g_H4h + (size_t)(m0 + row) * N + n0 + c * 8) = v;
        }
    } else {
        float* sf = (float*)dsm;                 // stride 132 floats
        #pragma unroll
        for (int mi = 0; mi < 4; mi++)
            #pragma unroll
            for (int ni = 0; ni < 4; ni++)
                #pragma unroll
                for (int hf = 0; hf < 2; hf++) {
                    int row = wm + mi * 16 + gq + hf * 8;
                    int col = wn + ni * 8 + tg * 2;
                    float2 v;
                    v.x = acc[mi][ni][hf * 2 + 0] + bias[n0 + col];
                    v.y = acc[mi][ni][hf * 2 + 1] + bias[n0 + col + 1];
                    *(float2*)(sf + row * 132 + col) = v;
                }
        __syncthreads();
        #pragma unroll
        for (int i = 0; i < 16; i++) {
            int idx = t + i * 256;               // 0..4095
            int row = idx >> 5, c = idx & 31;
            float4 v = *(float4*)(sf + row * 132 + c * 4);
            size_t off = (size_t)(m0 + row) * Dm + n0 + c * 4;
            uint2 xp = *(const uint2*)(g_X1h + off);
            float2 xa = __half22float2(*(__half2*)&xp.x);
            float2 xb = __half22float2(*(__half2*)&xp.y);
            v.x += xa.x; v.y += xa.y; v.z += xb.x; v.w += xb.y;
            *(float4*)(g_X2 + off) = v;
        }
    }
}

// ---------------------------------------------------------------------------
// Segmented SRU scan, pass A: 4 chains/thread, uint2 (4xfp16) loads.
// ---------------------------------------------------------------------------
__global__ void scanA()
{
    int t = blockIdx.x * blockDim.x + threadIdx.x;   // 0 .. NCH*NSEG/4-1
    int qb = (t & (NCH / 4 - 1)) << 2;               // chain base (mult of 4)
    int s  = t >> 11;                                // NCH/4 = 2048
    int b  = qb >> 9;
    int h  = qb & (Hh - 1);
    size_t base = ((size_t)b * Lseq + (size_t)s * SEGL) * Hh + h;

    float c0 = 0.f, c1 = 0.f, c2 = 0.f, c3 = 0.f;
    float p0 = 1.f, p1 = 1.f, p2 = 1.f, p3 = 1.f;
    #pragma unroll 4
    for (int l = 0; l < SEGL; ++l) {
        size_t i = base + (size_t)l * Hh;
        uint2 fr = *(const uint2*)(g_Fh + i);
        uint2 zr = *(const uint2*)(g_Zh + i);
        float2 fa = __half22float2(*(__half2*)&fr.x);
        float2 fb = __half22float2(*(__half2*)&fr.y);
        float2 za = __half22float2(*(__half2*)&zr.x);
        float2 zb = __half22float2(*(__half2*)&zr.y);
        c0 = fmaf(fa.x, c0 - za.x, za.x); p0 *= fa.x;
        c1 = fmaf(fa.y, c1 - za.y, za.y); p1 *= fa.y;
        c2 = fmaf(fb.x, c2 - zb.x, zb.x); p2 *= fb.x;
        c3 = fmaf(fb.y, c3 - zb.y, zb.y); p3 *= fb.y;
    }
    int idx = s * NCH + qb;
    *(float4*)(g_cend + idx) = make_float4(c0, c1, c2, c3);
    *(float4*)(g_pend + idx) = make_float4(p0, p1, p2, p3);
}

// ---------------------------------------------------------------------------
// Pass C fused with LayerNorm1.  Block = (b, seg): 256 threads x 2 chains
// (half2/float2 vectorized).  x read from g_Xh (fp16).
// ---------------------------------------------------------------------------
__global__ __launch_bounds__(256) void scanC_ln(
    const float* __restrict__ gamma,
    const float* __restrict__ beta)
{
    const int blk = blockIdx.x;          // 0..Bb*NSEG-1
    const int b   = blk >> 6;
    const int s   = blk & (NSEG - 1);
    const int tid = threadIdx.x;
    const int h0  = tid << 1;
    const int lane = tid & 31, w = tid >> 5;

    const size_t base = ((size_t)b * Lseq + (size_t)s * SEGL) * Hh + h0;
    const int q = (b << 9) | h0;

    // carry over earlier segments (<= 63 iterations, float2)
    float c0 = 0.f, c1 = 0.f;
    for (int sp = 0; sp < s; ++sp) {
        int idx = sp * NCH + q;
        float2 ce = *(const float2*)(g_cend + idx);
        float2 pe = *(const float2*)(g_pend + idx);
        c0 = fmaf(pe.x, c0, ce.x);
        c1 = fmaf(pe.y, c1, ce.y);
    }

    const float2 gg = *(const float2*)(gamma + h0);
    const float2 bb = *(const float2*)(beta  + h0);

    __shared__ float ssum[2][8], ssq[2][8];

    // prefetch step 0
    float2 f_n = __half22float2(*(const __half2*)(g_Fh + base));
    float2 z_n = __half22float2(*(const __half2*)(g_Zh + base));
    float2 r_n = __half22float2(*(const __half2*)(g_Rh + base));
    float2 x_n = __half22float2(*(const __half2*)(g_Xh + base));

    for (int l = 0; l < SEGL; ++l) {
        const float2 f = f_n, z = z_n, r = r_n, xv = x_n;
        if (l + 1 < SEGL) {
            size_t i = base + (size_t)(l + 1) * Hh;
            f_n = __half22float2(*(const __half2*)(g_Fh + i));
            z_n = __half22float2(*(const __half2*)(g_Zh + i));
            r_n = __half22float2(*(const __half2*)(g_Rh + i));
            x_n = __half22float2(*(const __half2*)(g_Xh + i));
        }

        c0 = fmaf(f.x, c0 - z.x, z.x);
        c1 = fmaf(f.y, c1 - z.y, z.y);
        const float hw0 = fmaf(r.x, c0 - xv.x, 2.0f * xv.x);
        const float hw1 = fmaf(r.y, c1 - xv.y, 2.0f * xv.y);

        float sv = hw0 + hw1;
        float sq = fmaf(hw0, hw0, hw1 * hw1);
        #pragma unroll
        for (int o = 16; o > 0; o >>= 1) {
            sv += __shfl_xor_sync(0xffffffffu, sv, o);
            sq += __shfl_xor_sync(0xffffffffu, sq, o);
        }
        const int pb = l & 1;
        if (lane == 0) { ssum[pb][w] = sv; ssq[pb][w] = sq; }
        __syncthreads();
        float S = 0.0f, SQ = 0.0f;
        #pragma unroll
        for (int k = 0; k < 8; k++) { S += ssum[pb][k]; SQ += ssq[pb][k]; }

        const float mean = S * (1.0f / 512.0f);
        const float var  = SQ * (1.0f / 512.0f) - mean * mean;
        const float rstd = rsqrtf(var + 1e-5f);

        *(__half2*)(g_X1h + base + (size_t)l * Hh) = __floats2half2_rn(
            (hw0 - mean) * rstd * gg.x + bb.x,
            (hw1 - mean) * rstd * gg.y + bb.y);
    }
}

// ---------------------------------------------------------------------------
// Final LayerNorm over 512: 1 block/row, 128 threads x float4.
// ---------------------------------------------------------------------------
__global__ void ln512_out(const float* __restrict__ gamma,
                          const float* __restrict__ beta,
                          float* __restrict__ outp)
{
    const float* in = (const float*)g_X2;

    size_t row = blockIdx.x;
    int t = threadIdx.x;

    float4 v = ((const float4*)(in + row * Dm))[t];
    float s  = v.x + v.y + v.z + v.w;
    float sq = v.x*v.x + v.y*v.y + v.z*v.z + v.w*v.w;

    #pragma unroll
    for (int o = 16; o > 0; o >>= 1) {
        s  += __shfl_xor_sync(0xffffffffu, s,  o);
        sq += __shfl_xor_sync(0xffffffffu, sq, o);
    }
    __shared__ float ssum[4], ssq[4];
    int w = t >> 5;
    if ((t & 31) == 0) { ssum[w] = s; ssq[w] = sq; }
    __syncthreads();
    float S  = ssum[0] + ssum[1] + ssum[2] + ssum[3];
    float SQ = ssq[0] + ssq[1] + ssq[2] + ssq[3];

    float mean = S * (1.0f / 512.0f);
    float var  = SQ * (1.0f / 512.0f) - mean * mean;
    float rstd = rsqrtf(var + 1e-5f);

    float4 gg = ((const float4*)gamma)[t];
    float4 bb = ((const float4*)beta)[t];
    float4 o4;
    o4.x = (v.x - mean) * rstd * gg.x + bb.x;
    o4.y = (v.y - mean) * rstd * gg.y + bb.y;
    o4.z = (v.z - mean) * rstd * gg.z + bb.z;
    o4.w = (v.w - mean) * rstd * gg.w + bb.w;
    ((float4*)(outp + row * Dm))[t] = o4;
}

// ---------------------------------------------------------------------------
// Launch.  scanC_ln stays at profiled slot (our launch index 3).
// ---------------------------------------------------------------------------
extern "C" void kernel_launch(void* const* d_in, const int* in_sizes, int n_in,
                              void* d_out, int out_size)
{
    const float* x    = (const float*)d_in[0];
    const float* Wsru = (const float*)d_in[1];
    const float* b_f  = (const float*)d_in[2];
    const float* b_r  = (const float*)d_in[3];
    const float* ln1g = (const float*)d_in[4];
    const float* ln1b = (const float*)d_in[5];
    const float* W1   = (const float*)d_in[6];
    const float* b1   = (const float*)d_in[7];
    const float* W2   = (const float*)d_in[8];
    const float* b2   = (const float*)d_in[9];
    const float* ln2g = (const float*)d_in[10];
    const float* ln2b = (const float*)d_in[11];
    float* out = (float*)d_out;

    static bool attr_done = false;
    if (!attr_done) {
        cudaFuncSetAttribute(gemm_h<0, 3 * Hh, Dm>,
                             cudaFuncAttributeMaxDynamicSharedMemorySize, GSMEM);
        cudaFuncSetAttribute(gemm_h<1, DFF, Dm>,
                             cudaFuncAttributeMaxDynamicSharedMemorySize, GSMEM);
        cudaFuncSetAttribute(gemm_h<2, Dm, DFF>,
                             cudaFuncAttributeMaxDynamicSharedMemorySize, GSMEM);
        attr_done = true;
    }

    // 0) all fp32 -> fp16 conversions                       [launch 0]
    f2h_all<<<(N8_TOT + 255) / 256, 256>>>(x, Wsru, W1, W2);
    // 1) u = x @ W_sru, fused gate sigmoids                 [launch 1]
    gemm_h<0, 3 * Hh, Dm><<<dim3((3 * Hh) / BN, MROWS / BM), 256, GSMEM>>>(b_f, b_r);
    // 2) segmented recurrence pass A                        [launch 2]
    scanA<<<(NCH * NSEG / 4) / 256, 256>>>();
    // 3) pass C (inline carries) fused with LN1 -> g_X1h    [launch 3 — profiled]
    scanC_ln<<<Bb * NSEG, 256>>>(ln1g, ln1b);
    // 4) h = gelu(x1 @ W1 + b1) -> g_H4h                    [launch 4]
    gemm_h<1, DFF, Dm><<<dim3(DFF / BN, MROWS / BM), 256, GSMEM>>>(b1, nullptr);
    // 5) x2 = x1 + h @ W2 + b2 -> g_X2                      [launch 5]
    gemm_h<2, Dm, DFF><<<dim3(Dm / BN, MROWS / BM), 256, GSMEM>>>(b2, nullptr);
    // 6) LN2 -> d_out                                       [launch 6]
    ln512_out<<<MROWS, 128>>>(ln2g, ln2b, out);
}

// round 11
// speedup vs baseline: 1.5085x; 1.0207x over previous
#include <cuda_runtime.h>
#include <cuda_fp16.h>
#include <cstdint>
#include <cstddef>

// ---------------------------------------------------------------------------
// Problem constants: B=16, L=4096, D=H=512
// ---------------------------------------------------------------------------
constexpr int Bb   = 16;
constexpr int Lseq = 4096;
constexpr int Dm   = 512;
constexpr int Hh   = 512;
constexpr int MROWS = Bb * Lseq;          // 65536
constexpr int DFF  = 2048;                // 4*D
constexpr int NSEG = 32;
constexpr int SEGL = Lseq / NSEG;         // 128
constexpr int NCH  = Bb * Hh;             // 8192 scan chains

// ---------------------------------------------------------------------------
// Scratch (device globals)
// ---------------------------------------------------------------------------
__device__ __align__(16) __half g_Xh   [(size_t)MROWS * Dm];
__device__ __align__(16) __half g_Wsruh[(size_t)Dm * 3 * Hh];
__device__ __align__(16) __half g_W1h  [(size_t)Dm * DFF];
__device__ __align__(16) __half g_W2h  [(size_t)DFF * Dm];
__device__ __align__(16) __half g_Zh   [(size_t)MROWS * Hh];
__device__ __align__(16) __half g_Fh   [(size_t)MROWS * Hh];
__device__ __align__(16) __half g_Rh   [(size_t)MROWS * Hh];
__device__ __align__(16) __half g_X1h  [(size_t)MROWS * Dm];
__device__ __align__(16) __half g_H4h  [(size_t)MROWS * DFF];
__device__ __align__(16) float  g_X2   [(size_t)MROWS * Dm];
__device__ __align__(16) float  g_cend [NCH * NSEG];
__device__ __align__(16) float  g_pend [NCH * NSEG];

// ---------------------------------------------------------------------------
// Helpers
// ---------------------------------------------------------------------------
__device__ __forceinline__ void cp16(uint32_t dst_s, const void* src) {
    asm volatile("cp.async.cg.shared.global [%0], [%1], 16;\n" :: "r"(dst_s), "l"(src));
}
__device__ __forceinline__ void cp_commit() { asm volatile("cp.async.commit_group;\n"); }
template<int NN>
__device__ __forceinline__ void cp_wait() { asm volatile("cp.async.wait_group %0;\n" :: "n"(NN)); }

__device__ __forceinline__ void ldsm_x4(uint32_t& r0, uint32_t& r1, uint32_t& r2, uint32_t& r3,
                                        uint32_t addr) {
    asm volatile("ldmatrix.sync.aligned.m8n8.x4.shared.b16 {%0,%1,%2,%3},[%4];\n"
                 : "=r"(r0), "=r"(r1), "=r"(r2), "=r"(r3) : "r"(addr));
}
__device__ __forceinline__ void ldsm_x4t(uint32_t& r0, uint32_t& r1, uint32_t& r2, uint32_t& r3,
                                         uint32_t addr) {
    asm volatile("ldmatrix.sync.aligned.m8n8.x4.trans.shared.b16 {%0,%1,%2,%3},[%4];\n"
                 : "=r"(r0), "=r"(r1), "=r"(r2), "=r"(r3) : "r"(addr));
}
__device__ __forceinline__ void mma16(float* c, const uint32_t* a, const uint32_t* b) {
    asm volatile(
        "mma.sync.aligned.m16n8k16.row.col.f32.f16.f16.f32 "
        "{%0,%1,%2,%3},{%4,%5,%6,%7},{%8,%9},{%0,%1,%2,%3};\n"
        : "+f"(c[0]), "+f"(c[1]), "+f"(c[2]), "+f"(c[3])
        : "r"(a[0]), "r"(a[1]), "r"(a[2]), "r"(a[3]), "r"(b[0]), "r"(b[1]));
}

__device__ __forceinline__ float sigmoidf_(float v) { return 1.0f / (1.0f + expf(-v)); }
__device__ __forceinline__ float gelu_(float v) {
    return 0.5f * v * (1.0f + erff(v * 0.70710678118654752440f));
}

// ---------------------------------------------------------------------------
// fp32 -> fp16, all four arrays in one launch
// ---------------------------------------------------------------------------
constexpr int N8_X  = (MROWS * Dm) / 8;
constexpr int N8_WS = (Dm * 3 * Hh) / 8;
constexpr int N8_W1 = (Dm * DFF) / 8;
constexpr int N8_W2 = (DFF * Dm) / 8;
constexpr int N8_TOT = N8_X + N8_WS + N8_W1 + N8_W2;

__global__ void f2h_all(const float* __restrict__ x,  const float* __restrict__ ws,
                        const float* __restrict__ w1, const float* __restrict__ w2) {
    int i = blockIdx.x * blockDim.x + threadIdx.x;
    const float* in; __half* out; int j;
    if (i < N8_X)                    { in = x;  out = g_Xh;    j = i; }
    else if (i < N8_X + N8_WS)       { in = ws; out = g_Wsruh; j = i - N8_X; }
    else if (i < N8_X + N8_WS + N8_W1) { in = w1; out = g_W1h; j = i - N8_X - N8_WS; }
    else if (i < N8_TOT)             { in = w2; out = g_W2h;   j = i - N8_X - N8_WS - N8_W1; }
    else return;
    const float4* src = (const float4*)in + (size_t)j * 2;
    float4 a = src[0], b = src[1];
    __half2 h[4];
    h[0] = __floats2half2_rn(a.x, a.y);
    h[1] = __floats2half2_rn(a.z, a.w);
    h[2] = __floats2half2_rn(b.x, b.y);
    h[3] = __floats2half2_rn(b.z, b.w);
    ((uint4*)out)[j] = *(uint4*)h;
}

// ---------------------------------------------------------------------------
// fp16 GEMM (R10-proven): tile 128x128x64, 3-stage cp.async, 256 thr,
// 2 CTA/SM, kt unroll x6, staged coalesced epilogues.
// ---------------------------------------------------------------------------
constexpr int BM = 128, BN = 128, BK = 64;
constexpr int STG_BYTES = BM * BK * 2 + BK * BN * 2;   // 32KB
constexpr int GSMEM = 3 * STG_BYTES;                    // 96KB dynamic

__device__ __forceinline__ uint32_t aoff(int r, int c) {
    return (uint32_t)(r * 128 + ((c ^ (r & 7)) << 4));
}
__device__ __forceinline__ uint32_t boff(int k, int c) {
    return (uint32_t)(k * 256 + ((c ^ (k & 7)) << 4));
}

template<int EPI, int N, int K>
__global__ __launch_bounds__(256, 2) void gemm_h(
    const float* __restrict__ bias,
    const float* __restrict__ bias2)
{
    extern __shared__ __align__(1024) char dsm[];

    const __half* __restrict__ A =
        (EPI == 0) ? g_Xh : ((EPI == 1) ? g_X1h : g_H4h);
    const __half* __restrict__ W =
        (EPI == 0) ? g_Wsruh : ((EPI == 1) ? g_W1h : g_W2h);

    const int t    = threadIdx.x;
    const int m0   = blockIdx.y * BM;
    const int n0   = blockIdx.x * BN;
    const int lane = t & 31, wid = t >> 5;
    const int gq   = lane >> 2, tg = lane & 3;
    const int wm   = (wid >> 2) * 64;
    const int wn   = (wid & 3) * 32;

    const uint32_t sBase = (uint32_t)__cvta_generic_to_shared(dsm);

    float acc[4][4][4];
    #pragma unroll
    for (int i = 0; i < 4; i++)
        #pragma unroll
        for (int j = 0; j < 4; j++)
            #pragma unroll
            for (int r = 0; r < 4; r++) acc[i][j][r] = 0.0f;

    auto loadChunk = [&](int kt, uint32_t aB) {
        const uint32_t bB = aB + BM * BK * 2;
        #pragma unroll
        for (int i = 0; i < 4; i++) {
            int idx = t + i * 256;
            int row = idx >> 3, c = idx & 7;
            cp16(aB + aoff(row, c),
                 A + (size_t)(m0 + row) * K + (size_t)kt * BK + c * 8);
        }
        #pragma unroll
        for (int i = 0; i < 4; i++) {
            int idx = t + i * 256;
            int row = idx >> 4, c = idx & 15;
            cp16(bB + boff(row, c),
                 W + (size_t)((size_t)kt * BK + row) * N + n0 + c * 8);
        }
        cp_commit();
    };

    const int KT = K / BK;
    loadChunk(0, sBase);
    if (KT > 1) loadChunk(1, sBase + STG_BYTES);

    const int ltile = lane >> 3;
    const int lrow  = lane & 7;

    uint32_t stg0 = sBase, stg1 = sBase + STG_BYTES, stg2 = sBase + 2u * STG_BYTES;

    #pragma unroll 6
    for (int kt = 0; kt < KT; ++kt) {
        if (kt + 2 <= KT) cp_wait<1>(); else cp_wait<0>();
        __syncthreads();
        if (kt + 2 < KT) loadChunk(kt + 2, stg2);

        const uint32_t aBase = stg0;
        const uint32_t bBase = stg0 + BM * BK * 2;

        #pragma unroll
        for (int ks = 0; ks < 4; ++ks) {
            uint32_t af[4][4], bf[4][2];
            #pragma unroll
            for (int mi = 0; mi < 4; mi++) {
                int row = wm + mi * 16 + ((ltile & 1) << 3) + lrow;
                int c   = ks * 2 + (ltile >> 1);
                ldsm_x4(af[mi][0], af[mi][1], af[mi][2], af[mi][3],
                        aBase + aoff(row, c));
            }
            #pragma unroll
            for (int ni2 = 0; ni2 < 2; ni2++) {
                int k = ks * 16 + ((ltile & 1) << 3) + lrow;
                int c = (wn >> 3) + ni2 * 2 + (ltile >> 1);
                uint32_t r0, r1, r2, r3;
                ldsm_x4t(r0, r1, r2, r3, bBase + boff(k, c));
                bf[ni2 * 2 + 0][0] = r0; bf[ni2 * 2 + 0][1] = r1;
                bf[ni2 * 2 + 1][0] = r2; bf[ni2 * 2 + 1][1] = r3;
            }
            #pragma unroll
            for (int mi = 0; mi < 4; mi++)
                #pragma unroll
                for (int ni = 0; ni < 4; ni++)
                    mma16(acc[mi][ni], af[mi], bf[ni]);
        }

        uint32_t tmp = stg0; stg0 = stg1; stg1 = stg2; stg2 = tmp;
    }

    // ---------------- staged epilogue (smem is dead: reuse it) --------------
    __syncthreads();

    if (EPI == 0) {
        const int seg = n0 >> 9;                 // tile fully in z|f|r region
        const int cb  = n0 - (seg << 9);
        const float* bp = (seg == 1) ? bias : bias2;
        __half* outp = (seg == 0) ? g_Zh : (seg == 1) ? g_Fh : g_Rh;
        __half* sh = (__half*)dsm;               // stride 136 halfs
        #pragma unroll
        for (int mi = 0; mi < 4; mi++)
            #pragma unroll
            for (int ni = 0; ni < 4; ni++)
                #pragma unroll
                for (int hf = 0; hf < 2; hf++) {
                    int row = wm + mi * 16 + gq + hf * 8;
                    int col = wn + ni * 8 + tg * 2;
                    float v0 = acc[mi][ni][hf * 2 + 0];
                    float v1 = acc[mi][ni][hf * 2 + 1];
                    if (seg != 0) {
                        v0 = sigmoidf_(v0 + bp[cb + col]);
                        v1 = sigmoidf_(v1 + bp[cb + col + 1]);
                    }
                    *(__half2*)(sh + row * 136 + col) = __floats2half2_rn(v0, v1);
                }
        __syncthreads();
        #pragma unroll
        for (int i = 0; i < 8; i++) {
            int idx = t + i * 256;
            int row = idx >> 4, c = idx & 15;
            uint4 v = *(uint4*)(sh + row * 136 + c * 8);
            *(uint4*)(outp + (size_t)(m0 + row) * Hh + cb + c * 8) = v;
        }
    } else if (EPI == 1) {
        __half* sh = (__half*)dsm;
        #pragma unroll
        for (int mi = 0; mi < 4; mi++)
            #pragma unroll
            for (int ni = 0; ni < 4; ni++)
                #pragma unroll
                for (int hf = 0; hf < 2; hf++) {
                    int row = wm + mi * 16 + gq + hf * 8;
                    int col = wn + ni * 8 + tg * 2;
                    float v0 = gelu_(acc[mi][ni][hf * 2 + 0] + bias[n0 + col]);
                    float v1 = gelu_(acc[mi][ni][hf * 2 + 1] + bias[n0 + col + 1]);
                    *(__half2*)(sh + row * 136 + col) = __floats2half2_rn(v0, v1);
                }
        __syncthreads();
        #pragma unroll
        for (int i = 0; i < 8; i++) {
            int idx = t + i * 256;
            int row = idx >> 4, c = idx & 15;
            uint4 v = *(uint4*)(sh + row * 136 + c * 8);
            *(uint4*)(g_H4h + (size_t)(m0 + row) * N + n0 + c * 8) = v;
        }
    } else {
        float* sf = (float*)dsm;                 // stride 132 floats
        #pragma unroll
        for (int mi = 0; mi < 4; mi++)
            #pragma unroll
            for (int ni = 0; ni < 4; ni++)
                #pragma unroll
                for (int hf = 0; hf < 2; hf++) {
                    int row = wm + mi * 16 + gq + hf * 8;
                    int col = wn + ni * 8 + tg * 2;
                    float2 v;
                    v.x = acc[mi][ni][hf * 2 + 0] + bias[n0 + col];
                    v.y = acc[mi][ni][hf * 2 + 1] + bias[n0 + col + 1];
                    *(float2*)(sf + row * 132 + col) = v;
                }
        __syncthreads();
        #pragma unroll
        for (int i = 0; i < 16; i++) {
            int idx = t + i * 256;               // 0..4095
            int row = idx >> 5, c = idx & 31;
            float4 v = *(float4*)(sf + row * 132 + c * 4);
            size_t off = (size_t)(m0 + row) * Dm + n0 + c * 4;
            uint2 xp = *(const uint2*)(g_X1h + off);
            float2 xa = __half22float2(*(__half2*)&xp.x);
            float2 xb = __half22float2(*(__half2*)&xp.y);
            v.x += xa.x; v.y += xa.y; v.z += xb.x; v.w += xb.y;
            *(float4*)(g_X2 + off) = v;
        }
    }
}

// ---------------------------------------------------------------------------
// Segmented SRU scan, pass A: 8 chains/thread, uint4 (8xfp16) loads.
// ---------------------------------------------------------------------------
__global__ void scanA()
{
    int t = blockIdx.x * blockDim.x + threadIdx.x;   // 0 .. NCH*NSEG/8-1
    int qb = (t & (NCH / 8 - 1)) << 3;               // chain base (mult of 8)
    int s  = t >> 10;                                // NCH/8 = 1024
    int b  = qb >> 9;
    int h  = qb & (Hh - 1);
    size_t base = ((size_t)b * Lseq + (size_t)s * SEGL) * Hh + h;

    float c[8], p[8];
    #pragma unroll
    for (int j = 0; j < 8; j++) { c[j] = 0.f; p[j] = 1.f; }

    #pragma unroll 4
    for (int l = 0; l < SEGL; ++l) {
        size_t i = base + (size_t)l * Hh;
        uint4 fr = *(const uint4*)(g_Fh + i);
        uint4 zr = *(const uint4*)(g_Zh + i);
        const uint32_t* fw = (const uint32_t*)&fr;
        const uint32_t* zw = (const uint32_t*)&zr;
        #pragma unroll
        for (int v = 0; v < 4; v++) {
            float2 f2 = __half22float2(*(__half2*)&fw[v]);
            float2 z2 = __half22float2(*(__half2*)&zw[v]);
            c[v*2+0] = fmaf(f2.x, c[v*2+0] - z2.x, z2.x); p[v*2+0] *= f2.x;
            c[v*2+1] = fmaf(f2.y, c[v*2+1] - z2.y, z2.y); p[v*2+1] *= f2.y;
        }
    }
    int idx = s * NCH + qb;
    *(float4*)(g_cend + idx)     = make_float4(c[0], c[1], c[2], c[3]);
    *(float4*)(g_cend + idx + 4) = make_float4(c[4], c[5], c[6], c[7]);
    *(float4*)(g_pend + idx)     = make_float4(p[0], p[1], p[2], p[3]);
    *(float4*)(g_pend + idx + 4) = make_float4(p[4], p[5], p[6], p[7]);
}

// ---------------------------------------------------------------------------
// Pass C fused with LayerNorm1, BATCHED: 8 timesteps per __syncthreads.
// Block = (b, seg): 256 threads x 2 chains.  Butterfly-reduced step-sums are
// valid in ALL lanes, so lanes 0..7 store the 8 step totals in parallel.
// ---------------------------------------------------------------------------
__global__ __launch_bounds__(256) void scanC_ln(
    const float* __restrict__ gamma,
    const float* __restrict__ beta)
{
    const int blk = blockIdx.x;          // 0..Bb*NSEG-1
    const int b   = blk >> 5;
    const int s   = blk & (NSEG - 1);
    const int tid = threadIdx.x;
    const int h0  = tid << 1;
    const int lane = tid & 31, w = tid >> 5;

    const size_t base = ((size_t)b * Lseq + (size_t)s * SEGL) * Hh + h0;
    const int q = (b << 9) | h0;

    // carry over earlier segments (<= 31 iterations, float2)
    float c0 = 0.f, c1 = 0.f;
    for (int sp = 0; sp < s; ++sp) {
        int idx = sp * NCH + q;
        float2 ce = *(const float2*)(g_cend + idx);
        float2 pe = *(const float2*)(g_pend + idx);
        c0 = fmaf(pe.x, c0, ce.x);
        c1 = fmaf(pe.y, c1, ce.y);
    }

    const float2 gg = *(const float2*)(gamma + h0);
    const float2 bb = *(const float2*)(beta  + h0);

    __shared__ float ssum[2][8][8], ssq[2][8][8];   // [buf][warp][step]

    for (int l0 = 0; l0 < SEGL; l0 += 8) {
        float hw0[8], hw1[8], ps[8], pq[8];
        #pragma unroll
        for (int j = 0; j < 8; j++) {
            size_t i = base + (size_t)(l0 + j) * Hh;
            float2 f  = __half22float2(*(const __half2*)(g_Fh + i));
            float2 z  = __half22float2(*(const __half2*)(g_Zh + i));
            float2 r  = __half22float2(*(const __half2*)(g_Rh + i));
            float2 xv = __half22float2(*(const __half2*)(g_Xh + i));
            c0 = fmaf(f.x, c0 - z.x, z.x);
            c1 = fmaf(f.y, c1 - z.y, z.y);
            hw0[j] = fmaf(r.x, c0 - xv.x, 2.0f * xv.x);
            hw1[j] = fmaf(r.y, c1 - xv.y, 2.0f * xv.y);
            ps[j] = hw0[j] + hw1[j];
            pq[j] = fmaf(hw0[j], hw0[j], hw1[j] * hw1[j]);
        }
        #pragma unroll
        for (int j = 0; j < 8; j++) {
            #pragma unroll
            for (int o = 16; o > 0; o >>= 1) {
                ps[j] += __shfl_xor_sync(0xffffffffu, ps[j], o);
                pq[j] += __shfl_xor_sync(0xffffffffu, pq[j], o);
            }
        }
        const int pb = (l0 >> 3) & 1;
        if (lane < 8) {                        // all lanes hold totals; 0..7 store
            ssum[pb][w][lane] = ps[lane];
            ssq [pb][w][lane] = pq[lane];
        }
        __syncthreads();
        #pragma unroll
        for (int j = 0; j < 8; j++) {
            float S = 0.f, SQ = 0.f;
            #pragma unroll
            for (int k = 0; k < 8; k++) { S += ssum[pb][k][j]; SQ += ssq[pb][k][j]; }
            const float mean = S * (1.0f / 512.0f);
            const float var  = SQ * (1.0f / 512.0f) - mean * mean;
            const float rstd = rsqrtf(var + 1e-5f);
            *(__half2*)(g_X1h + base + (size_t)(l0 + j) * Hh) = __floats2half2_rn(
                (hw0[j] - mean) * rstd * gg.x + bb.x,
                (hw1[j] - mean) * rstd * gg.y + bb.y);
        }
    }
}

// ---------------------------------------------------------------------------
// Final LayerNorm over 512: 1 block/row, 128 threads x float4.
// ---------------------------------------------------------------------------
__global__ void ln512_out(const float* __restrict__ gamma,
                          const float* __restrict__ beta,
                          float* __restrict__ outp)
{
    const float* in = (const float*)g_X2;

    size_t row = blockIdx.x;
    int t = threadIdx.x;

    float4 v = ((const float4*)(in + row * Dm))[t];
    float s  = v.x + v.y + v.z + v.w;
    float sq = v.x*v.x + v.y*v.y + v.z*v.z + v.w*v.w;

    #pragma unroll
    for (int o = 16; o > 0; o >>= 1) {
        s  += __shfl_xor_sync(0xffffffffu, s,  o);
        sq += __shfl_xor_sync(0xffffffffu, sq, o);
    }
    __shared__ float ssum[4], ssq[4];
    int w = t >> 5;
    if ((t & 31) == 0) { ssum[w] = s; ssq[w] = sq; }
    __syncthreads();
    float S  = ssum[0] + ssum[1] + ssum[2] + ssum[3];
    float SQ = ssq[0] + ssq[1] + ssq[2] + ssq[3];

    float mean = S * (1.0f / 512.0f);
    float var  = SQ * (1.0f / 512.0f) - mean * mean;
    float rstd = rsqrtf(var + 1e-5f);

    float4 gg = ((const float4*)gamma)[t];
    float4 bb = ((const float4*)beta)[t];
    float4 o4;
    o4.x = (v.x - mean) * rstd * gg.x + bb.x;
    o4.y = (v.y - mean) * rstd * gg.y + bb.y;
    o4.z = (v.z - mean) * rstd * gg.z + bb.z;
    o4.w = (v.w - mean) * rstd * gg.w + bb.w;
    ((float4*)(outp + row * Dm))[t] = o4;
}

// ---------------------------------------------------------------------------
// Launch.  scanC_ln stays at profiled slot (our launch index 3).
// ---------------------------------------------------------------------------
extern "C" void kernel_launch(void* const* d_in, const int* in_sizes, int n_in,
                              void* d_out, int out_size)
{
    const float* x    = (const float*)d_in[0];
    const float* Wsru = (const float*)d_in[1];
    const float* b_f  = (const float*)d_in[2];
    const float* b_r  = (const float*)d_in[3];
    const float* ln1g = (const float*)d_in[4];
    const float* ln1b = (const float*)d_in[5];
    const float* W1   = (const float*)d_in[6];
    const float* b1   = (const float*)d_in[7];
    const float* W2   = (const float*)d_in[8];
    const float* b2   = (const float*)d_in[9];
    const float* ln2g = (const float*)d_in[10];
    const float* ln2b = (const float*)d_in[11];
    float* out = (float*)d_out;

    static bool attr_done = false;
    if (!attr_done) {
        cudaFuncSetAttribute(gemm_h<0, 3 * Hh, Dm>,
                             cudaFuncAttributeMaxDynamicSharedMemorySize, GSMEM);
        cudaFuncSetAttribute(gemm_h<1, DFF, Dm>,
                             cudaFuncAttributeMaxDynamicSharedMemorySize, GSMEM);
        cudaFuncSetAttribute(gemm_h<2, Dm, DFF>,
                             cudaFuncAttributeMaxDynamicSharedMemorySize, GSMEM);
        attr_done = true;
    }

    // 0) all fp32 -> fp16 conversions                       [launch 0]
    f2h_all<<<(N8_TOT + 255) / 256, 256>>>(x, Wsru, W1, W2);
    // 1) u = x @ W_sru, fused gate sigmoids                 [launch 1]
    gemm_h<0, 3 * Hh, Dm><<<dim3((3 * Hh) / BN, MROWS / BM), 256, GSMEM>>>(b_f, b_r);
    // 2) segmented recurrence pass A                        [launch 2]
    scanA<<<(NCH * NSEG / 8) / 256, 256>>>();
    // 3) pass C batched, fused with LN1 -> g_X1h            [launch 3 — profiled]
    scanC_ln<<<Bb * NSEG, 256>>>(ln1g, ln1b);
    // 4) h = gelu(x1 @ W1 + b1) -> g_H4h                    [launch 4]
    gemm_h<1, DFF, Dm><<<dim3(DFF / BN, MROWS / BM), 256, GSMEM>>>(b1, nullptr);
    // 5) x2 = x1 + h @ W2 + b2 -> g_X2                      [launch 5]
    gemm_h<2, Dm, DFF><<<dim3(Dm / BN, MROWS / BM), 256, GSMEM>>>(b2, nullptr);
    // 6) LN2 -> d_out                                       [launch 6]
    ln512_out<<<MROWS, 128>>>(ln2g, ln2b, out);
}